// round 4
// baseline (speedup 1.0000x reference)
#include <cuda_runtime.h>

// GraphSAGE 3-layer, mean aggregation.
// Per layer:  Y[i, 0:128]   = h[i] @ Wl^T
//             Y[i, 128:256] = h[i] @ Wr^T + b
//             h'[i, n] = act( deg_inv[i] * sum_{j in N(i)} Y[j, n]  +  Y[i, 128+n] )
// CSR (by dst) rebuilt every launch from edge_index.
// edge_index dtype (int64 vs int32) detected at runtime device-side.
// Inputs identified by element count (robust to slot reordering).

#define NN 100000
#define NE 1600000
#define DD 128
#define SCAN_B 1024
#define NSB 98          // ceil(100000 / 1024)

// ---------------- static device scratch (no allocations allowed) ----------------
__device__ int   g_deg[NN];
__device__ int   g_fill[NN];
__device__ int   g_rowptr[NN];
__device__ float g_deginv[NN];
__device__ int   g_col[NE];
__device__ int   g_bsum[NSB];
__device__ int   g_is64;
__device__ __align__(16) float g_Y[NN * 256];     // fused [Yl | Yr]
__device__ __align__(16) float g_hA[NN * DD];
__device__ __align__(16) float g_hB[NN * DD];

// ---------------- edge_index dtype detection ----------------
// If the buffer holds int64 values < 2^31, every odd 32-bit word is 0.
// If it holds int32 node ids (~uniform in [0,100000)), odd words are ~never all 0.
__global__ void k_detect(const int* __restrict__ ei32) {
    __shared__ int nz;
    if (threadIdx.x == 0) nz = 0;
    __syncthreads();
    int local = 0;
    for (int i = threadIdx.x; i < 4096; i += blockDim.x)
        if (ei32[2 * i + 1] != 0) local = 1;
    if (local) atomicOr(&nz, 1);
    __syncthreads();
    if (threadIdx.x == 0) g_is64 = (nz == 0) ? 1 : 0;
}

__device__ __forceinline__ int load_edge(const void* ei, int idx, int is64) {
    // idx in [0, 2*NE): 0..NE-1 = src, NE..2*NE-1 = dst
    int v;
    if (is64) v = (int)((const long long*)ei)[idx];
    else      v = ((const int*)ei)[idx];
    // clamp: turn any surprise into wrong-answer signal, not a device crash
    v = v < 0 ? 0 : (v >= NN ? NN - 1 : v);
    return v;
}

// ---------------- CSR build ----------------
__global__ void k_zero() {
    int i = blockIdx.x * blockDim.x + threadIdx.x;
    if (i < NN) { g_deg[i] = 0; g_fill[i] = 0; }
}

__global__ void k_hist(const void* __restrict__ ei) {
    int e = blockIdx.x * blockDim.x + threadIdx.x;
    if (e < NE) {
        int d = load_edge(ei, NE + e, g_is64);
        atomicAdd(&g_deg[d], 1);
    }
}

__global__ void k_scan_local() {
    __shared__ int s[2][SCAN_B];
    int t   = threadIdx.x;
    int gid = blockIdx.x * SCAN_B + t;
    int v   = (gid < NN) ? g_deg[gid] : 0;
    int cur = 0;
    s[0][t] = v;
    __syncthreads();
    for (int off = 1; off < SCAN_B; off <<= 1) {
        int add = (t >= off) ? s[cur][t - off] : 0;
        s[cur ^ 1][t] = s[cur][t] + add;
        cur ^= 1;
        __syncthreads();
    }
    int incl = s[cur][t];
    if (gid < NN) g_rowptr[gid] = incl - v;           // exclusive within block
    if (t == SCAN_B - 1) g_bsum[blockIdx.x] = incl;   // block total
}

__global__ void k_scan_off() {
    if (blockIdx.x == 0 && threadIdx.x == 0) {
        int run = 0;
        for (int b = 0; b < NSB; b++) { int tmp = g_bsum[b]; g_bsum[b] = run; run += tmp; }
    }
}

__global__ void k_scan_add() {
    int gid = blockIdx.x * SCAN_B + threadIdx.x;
    if (gid < NN) {
        g_rowptr[gid] += g_bsum[blockIdx.x];
        int d = g_deg[gid];
        g_deginv[gid] = 1.0f / (float)(d > 1 ? d : 1);
    }
}

__global__ void k_fill(const void* __restrict__ ei) {
    int e = blockIdx.x * blockDim.x + threadIdx.x;
    if (e < NE) {
        int is64 = g_is64;
        int d   = load_edge(ei, NE + e, is64);
        int s   = load_edge(ei, e, is64);
        int pos = g_rowptr[d] + atomicAdd(&g_fill[d], 1);
        g_col[pos] = s;
    }
}

// ---------------- fused dual GEMM:  Y = A @ [Wl^T | Wr^T]  (+bias on right half) ----------------
// A: [NN, 128] fp32.  Block tile: 64 rows x 256 cols, K-tiled by 32.
// 256 threads; thread (tr = tid>>5, tc = tid&31) computes an 8x8 microtile
// at rows tr*8.., cols tc + 32*c  (column-interleaved -> conflict-free LDS).
__device__ __forceinline__ const float* pick_src(const float* x, int sel) {
    return sel == 0 ? x : (sel == 1 ? g_hA : g_hB);
}

__global__ void __launch_bounds__(256) k_gemm(
    const float* __restrict__ xin, int srcSel,
    const float* __restrict__ Wl, const float* __restrict__ Wr,
    const float* __restrict__ bias)
{
    __shared__ __align__(16) float sA[64 * 32];    // [row][k]  8 KB
    __shared__ __align__(16) float sB[32 * 256];   // [k][n]   32 KB

    const float* A = pick_src(xin, srcSel);
    const float4* A4  = (const float4*)A;
    const float4* Wl4 = (const float4*)Wl;
    const float4* Wr4 = (const float4*)Wr;

    int tid = threadIdx.x;
    int tr = tid >> 5, tc = tid & 31;
    int rowBase = blockIdx.x * 64;

    float acc[8][8];
#pragma unroll
    for (int r = 0; r < 8; r++)
#pragma unroll
        for (int c = 0; c < 8; c++) acc[r][c] = 0.0f;

#pragma unroll 1
    for (int kt = 0; kt < 4; kt++) {
        // A tile: 64 rows x 32 k = 512 float4, 2 per thread
#pragma unroll
        for (int it = 0; it < 2; it++) {
            int idx = it * 256 + tid;          // 0..511
            int r = idx >> 3, kq = idx & 7;    // row, float4-within-row
            int grow = rowBase + r;
            float4 v = make_float4(0.f, 0.f, 0.f, 0.f);
            if (grow < NN) v = __ldg(&A4[grow * 32 + kt * 8 + kq]);
            ((float4*)sA)[idx] = v;
        }
        // B tile: [32][256]; thread owns column n = tid; transpose-on-store
#pragma unroll
        for (int i = 0; i < 8; i++) {
            int n = tid;
            float4 w = (n < 128) ? __ldg(&Wl4[n * 32 + kt * 8 + i])
                                 : __ldg(&Wr4[(n - 128) * 32 + kt * 8 + i]);
            sB[(i * 4 + 0) * 256 + n] = w.x;
            sB[(i * 4 + 1) * 256 + n] = w.y;
            sB[(i * 4 + 2) * 256 + n] = w.z;
            sB[(i * 4 + 3) * 256 + n] = w.w;
        }
        __syncthreads();

#pragma unroll 4
        for (int k = 0; k < 32; k++) {
            float a[8], b[8];
#pragma unroll
            for (int r = 0; r < 8; r++) a[r] = sA[(tr * 8 + r) * 32 + k];   // broadcast
#pragma unroll
            for (int c = 0; c < 8; c++) b[c] = sB[k * 256 + tc + 32 * c];   // conflict-free
#pragma unroll
            for (int r = 0; r < 8; r++)
#pragma unroll
                for (int c = 0; c < 8; c++) acc[r][c] = fmaf(a[r], b[c], acc[r][c]);
        }
        __syncthreads();
    }

    // epilogue: bias on right half, store to Y
#pragma unroll
    for (int r = 0; r < 8; r++) {
        int grow = rowBase + tr * 8 + r;
        if (grow < NN) {
#pragma unroll
            for (int c = 0; c < 8; c++) {
                int n = tc + 32 * c;
                float v = acc[r][c];
                if (n >= 128) v += bias[n - 128];
                g_Y[grow * 256 + n] = v;
            }
        }
    }
}

// ---------------- combine: gather-mean over CSR + self term (+ReLU) ----------------
// One warp per dst node; lane owns float4 (4 of the 128 features).
// Index prefetch overlaps the g_col load with the Y gather.
template <bool RELU>
__global__ void __launch_bounds__(256) k_combine(float* __restrict__ outx, int dstSel)
{
    int w    = (blockIdx.x * blockDim.x + threadIdx.x) >> 5;
    int lane = threadIdx.x & 31;
    if (w >= NN) return;

    const float4* __restrict__ Y4 = (const float4*)g_Y;   // row = 64 float4 (256 floats)
    int base = g_rowptr[w];
    int cnt  = g_deg[w];

    float4 acc = make_float4(0.f, 0.f, 0.f, 0.f);

    if (cnt > 0) {
        int jNext = __ldg(&g_col[base]);
#pragma unroll 1
        for (int t = 0; t < cnt - 1; t++) {
            int j = jNext;
            jNext = __ldg(&g_col[base + t + 1]);         // prefetch next index
            float4 v = __ldg(&Y4[j * 64 + lane]);        // left half of row j
            acc.x += v.x; acc.y += v.y; acc.z += v.z; acc.w += v.w;
        }
        float4 v = __ldg(&Y4[jNext * 64 + lane]);
        acc.x += v.x; acc.y += v.y; acc.z += v.z; acc.w += v.w;
    }

    float di = g_deginv[w];
    float4 rr = __ldg(&Y4[w * 64 + 32 + lane]);          // right half of own row (has bias)

    float4 o;
    o.x = fmaf(acc.x, di, rr.x);
    o.y = fmaf(acc.y, di, rr.y);
    o.z = fmaf(acc.z, di, rr.z);
    o.w = fmaf(acc.w, di, rr.w);
    if (RELU) {
        o.x = fmaxf(o.x, 0.f); o.y = fmaxf(o.y, 0.f);
        o.z = fmaxf(o.z, 0.f); o.w = fmaxf(o.w, 0.f);
    }

    float4* dst = (dstSel == 0) ? (float4*)outx
                : (dstSel == 1) ? (float4*)g_hA : (float4*)g_hB;
    dst[w * 32 + lane] = o;
}

// ---------------- launch ----------------
extern "C" void kernel_launch(void* const* d_in, const int* in_sizes, int n_in,
                              void* d_out, int out_size)
{
    // Identify big tensors by element count (robust to slot order):
    //   x = NN*DD = 12.8M, edge_index = 2*NE = 3.2M, edge_attr = NE = 1.6M.
    // Weights (16384 ea) / biases (128 ea) keep their relative metadata order:
    //   W1l, b1, W1r, W2l, b2, W2r, W3l, b3, W3r.
    const float* x  = nullptr;
    const void*  ei = nullptr;
    const float* Wm[6] = {nullptr, nullptr, nullptr, nullptr, nullptr, nullptr};
    const float* Bm[3] = {nullptr, nullptr, nullptr};
    int nw = 0, nb = 0;
    for (int i = 0; i < n_in; i++) {
        long long sz = in_sizes[i];
        if (sz == (long long)NN * DD)      x  = (const float*)d_in[i];
        else if (sz == (long long)2 * NE)  ei = d_in[i];
        else if (sz == (long long)NE)      { /* edge_attr, unused */ }
        else if (sz == DD * DD)            { if (nw < 6) Wm[nw++] = (const float*)d_in[i]; }
        else if (sz == DD)                 { if (nb < 3) Bm[nb++] = (const float*)d_in[i]; }
    }
    const float* W1l = Wm[0]; const float* W1r = Wm[1];
    const float* W2l = Wm[2]; const float* W2r = Wm[3];
    const float* W3l = Wm[4]; const float* W3r = Wm[5];
    const float* b1 = Bm[0]; const float* b2 = Bm[1]; const float* b3 = Bm[2];
    float* out = (float*)d_out;
    if (!x || !ei || nw < 6 || nb < 3) return;   // layout surprise -> fail loudly via rel_err

    const int EB = (NE + 255) / 256;          // 6250
    const int NB = (NN + 255) / 256;          // 391
    const int GB = (NN + 63) / 64;            // 1563 gemm blocks
    const int CB = (NN * 32 + 255) / 256;     // 12500 combine blocks (warp/node)

    // CSR build (every launch; graph-capturable, kernels only)
    k_detect<<<1, 256>>>((const int*)ei);
    k_zero<<<NB, 256>>>();
    k_hist<<<EB, 256>>>(ei);
    k_scan_local<<<NSB, SCAN_B>>>();
    k_scan_off<<<1, 32>>>();
    k_scan_add<<<NSB, SCAN_B>>>();
    k_fill<<<EB, 256>>>(ei);

    // layer 1: x -> hA (ReLU)
    k_gemm<<<GB, 256>>>(x, 0, W1l, W1r, b1);
    k_combine<true><<<CB, 256>>>(out, 1);

    // layer 2: hA -> hB (ReLU)
    k_gemm<<<GB, 256>>>(x, 1, W2l, W2r, b2);
    k_combine<true><<<CB, 256>>>(out, 2);

    // layer 3: hB -> out (no ReLU)
    k_gemm<<<GB, 256>>>(x, 2, W3l, W3r, b3);
    k_combine<false><<<CB, 256>>>(out, 0);
}

// round 6
// speedup vs baseline: 1.3432x; 1.3432x over previous
#include <cuda_runtime.h>
#include <cuda_bf16.h>
#include <cstdint>

// GraphSAGE 3-layer, mean aggregation — mma.sync bf16-compensated GEMM (sm_100-safe).
// Per layer:  Y[i, 0:128]   = h[i] @ Wl^T
//             Y[i, 128:256] = h[i] @ Wr^T + b
//             h'[i, n] = act( deg_inv[i] * sum_{j in N(i)} Y[j, n]  +  Y[i, 128+n] )
// GEMM: operands split hi/lo bf16; D = Ahi*Bhi + Ahi*Blo + Alo*Bhi, fp32 accum.

#define NN 100000
#define NE 1600000
#define DD 128
#define SCAN_B 1024
#define NSB 98
#define MTILE 64
#define GRIDM 1563                 // ceil(100000/64)
#define PADN (GRIDM * MTILE)       // 100032

// ---------------- static device scratch ----------------
__device__ int   g_deg[NN];
__device__ int   g_fill[NN];
__device__ int   g_rowptr[NN];
__device__ float g_deginv[NN];
__device__ int   g_col[NE];
__device__ int   g_bsum[NSB];
__device__ int   g_is64;
__device__ __align__(16) float g_Y[(size_t)NN * 256];
__device__ __align__(16) __nv_bfloat16 g_Ahi[(size_t)PADN * DD];
__device__ __align__(16) __nv_bfloat16 g_Alo[(size_t)PADN * DD];
__device__ __align__(16) __nv_bfloat16 g_Bhi[3 * 256 * DD];
__device__ __align__(16) __nv_bfloat16 g_Blo[3 * 256 * DD];

// ---------------- helpers ----------------
__device__ __forceinline__ uint32_t smem_u32(const void* p) {
    uint32_t a;
    asm("{ .reg .u64 t; cvta.to.shared.u64 t, %1; cvt.u32.u64 %0, t; }" : "=r"(a) : "l"(p));
    return a;
}
__device__ __forceinline__ void ldmatrix_x4(uint32_t& r0, uint32_t& r1, uint32_t& r2, uint32_t& r3, uint32_t addr) {
    asm volatile("ldmatrix.sync.aligned.m8n8.x4.shared.b16 {%0,%1,%2,%3}, [%4];"
                 : "=r"(r0), "=r"(r1), "=r"(r2), "=r"(r3) : "r"(addr));
}
__device__ __forceinline__ void mma_bf16(float* c, const uint32_t* a, const uint32_t* b) {
    asm volatile("mma.sync.aligned.m16n8k16.row.col.f32.bf16.bf16.f32 "
                 "{%0,%1,%2,%3}, {%4,%5,%6,%7}, {%8,%9}, {%0,%1,%2,%3};"
                 : "+f"(c[0]), "+f"(c[1]), "+f"(c[2]), "+f"(c[3])
                 : "r"(a[0]), "r"(a[1]), "r"(a[2]), "r"(a[3]), "r"(b[0]), "r"(b[1]));
}
__device__ __forceinline__ unsigned short f2bf(float f) {
    __nv_bfloat16 h = __float2bfloat16_rn(f);
    return *reinterpret_cast<unsigned short*>(&h);
}
__device__ __forceinline__ float bf2f(unsigned short u) {
    __nv_bfloat16 h = *reinterpret_cast<__nv_bfloat16*>(&u);
    return __bfloat162float(h);
}
// split float4 -> hi/lo bf16 quads, store row-major at (row,col..col+3)
__device__ __forceinline__ void store_hilo_rm(
    __nv_bfloat16* bh, __nv_bfloat16* bl, size_t row, int col, float4 v)
{
    unsigned short hx = f2bf(v.x), hy = f2bf(v.y), hz = f2bf(v.z), hw = f2bf(v.w);
    uint2 uh = make_uint2((uint32_t)hx | ((uint32_t)hy << 16),
                          (uint32_t)hz | ((uint32_t)hw << 16));
    unsigned short lx = f2bf(v.x - bf2f(hx)), ly = f2bf(v.y - bf2f(hy));
    unsigned short lz = f2bf(v.z - bf2f(hz)), lw = f2bf(v.w - bf2f(hw));
    uint2 ul = make_uint2((uint32_t)lx | ((uint32_t)ly << 16),
                          (uint32_t)lz | ((uint32_t)lw << 16));
    *(uint2*)(bh + row * DD + col) = uh;
    *(uint2*)(bl + row * DD + col) = ul;
}

// ---------------- edge_index dtype detection ----------------
__global__ void k_detect(const int* __restrict__ ei32) {
    __shared__ int nz;
    if (threadIdx.x == 0) nz = 0;
    __syncthreads();
    int local = 0;
    for (int i = threadIdx.x; i < 4096; i += blockDim.x)
        if (ei32[2 * i + 1] != 0) local = 1;
    if (local) atomicOr(&nz, 1);
    __syncthreads();
    if (threadIdx.x == 0) g_is64 = (nz == 0) ? 1 : 0;
}
__device__ __forceinline__ int load_edge(const void* ei, int idx, int is64) {
    int v;
    if (is64) v = (int)((const long long*)ei)[idx];
    else      v = ((const int*)ei)[idx];
    v = v < 0 ? 0 : (v >= NN ? NN - 1 : v);
    return v;
}

// ---------------- CSR build ----------------
__global__ void k_zero() {
    int i = blockIdx.x * blockDim.x + threadIdx.x;
    if (i < NN) { g_deg[i] = 0; g_fill[i] = 0; }
}
__global__ void k_hist(const void* __restrict__ ei) {
    int e = blockIdx.x * blockDim.x + threadIdx.x;
    if (e < NE) atomicAdd(&g_deg[load_edge(ei, NE + e, g_is64)], 1);
}
__global__ void k_scan_local() {
    __shared__ int s[2][SCAN_B];
    int t = threadIdx.x, gid = blockIdx.x * SCAN_B + t;
    int v = (gid < NN) ? g_deg[gid] : 0;
    int cur = 0;
    s[0][t] = v;
    __syncthreads();
    for (int off = 1; off < SCAN_B; off <<= 1) {
        int add = (t >= off) ? s[cur][t - off] : 0;
        s[cur ^ 1][t] = s[cur][t] + add;
        cur ^= 1;
        __syncthreads();
    }
    int incl = s[cur][t];
    if (gid < NN) g_rowptr[gid] = incl - v;
    if (t == SCAN_B - 1) g_bsum[blockIdx.x] = incl;
}
__global__ void k_scan_off() {
    if (blockIdx.x == 0 && threadIdx.x == 0) {
        int run = 0;
        for (int b = 0; b < NSB; b++) { int tmp = g_bsum[b]; g_bsum[b] = run; run += tmp; }
    }
}
__global__ void k_scan_add() {
    int gid = blockIdx.x * SCAN_B + threadIdx.x;
    if (gid < NN) {
        g_rowptr[gid] += g_bsum[blockIdx.x];
        int d = g_deg[gid];
        g_deginv[gid] = 1.0f / (float)(d > 1 ? d : 1);
    }
}
__global__ void k_fill(const void* __restrict__ ei) {
    int e = blockIdx.x * blockDim.x + threadIdx.x;
    if (e < NE) {
        int is64 = g_is64;
        int d = load_edge(ei, NE + e, is64);
        int s = load_edge(ei, e, is64);
        int pos = g_rowptr[d] + atomicAdd(&g_fill[d], 1);
        g_col[pos] = s;
    }
}

// ---------------- prep: x -> A hi/lo (row-major) ----------------
__global__ void k_prepA(const float* __restrict__ x) {
    int id = blockIdx.x * blockDim.x + threadIdx.x;      // PADN*32
    if (id >= PADN * 32) return;
    int row = id >> 5, k4 = id & 31;
    float4 v = make_float4(0.f, 0.f, 0.f, 0.f);
    if (row < NN) v = __ldg((const float4*)(x + (size_t)row * DD + k4 * 4));
    store_hilo_rm(g_Ahi, g_Alo, row, k4 * 4, v);
}

// ---------------- prep: weights -> B hi/lo ([layer][n][k], n<128 = Wl row, else Wr) ----------------
__global__ void k_prepW(const float* __restrict__ W1l, const float* __restrict__ W1r,
                        const float* __restrict__ W2l, const float* __restrict__ W2r,
                        const float* __restrict__ W3l, const float* __restrict__ W3r) {
    int id = blockIdx.x * blockDim.x + threadIdx.x;      // 3*256*32
    if (id >= 3 * 256 * 32) return;
    int layer = id / (256 * 32);
    int rem = id % (256 * 32);
    int n = rem / 32, k4 = rem % 32;
    const float* Wl = layer == 0 ? W1l : (layer == 1 ? W2l : W3l);
    const float* Wr = layer == 0 ? W1r : (layer == 1 ? W2r : W3r);
    const float* row = (n < 128) ? (Wl + n * DD) : (Wr + (n - 128) * DD);
    float4 v = __ldg((const float4*)(row + k4 * 4));
    store_hilo_rm(g_Bhi + (size_t)layer * 256 * DD, g_Blo + (size_t)layer * 256 * DD, n, k4 * 4, v);
}

// ---------------- mma.sync GEMM: Y[64 rows x 256] = A @ B^T (+bias on cols>=128) ----------------
// 8 warps: wm = wid&1 (row group of 32), wn = wid>>1 (col group of 64).
// A hi/lo staged in smem with 16B-column XOR swizzle; B fragments from global (L1/L2 resident).
__global__ void __launch_bounds__(256) k_gemm_mma(int layer, const float* __restrict__ bias) {
    __shared__ __align__(16) unsigned char sA[2][64 * 256];   // [hi/lo][64 rows x 128 bf16]
    __shared__ float sBias[128];

    int tid = threadIdx.x, wid = tid >> 5, lane = tid & 31;
    int rowBase = blockIdx.x * MTILE;

    // stage A hi/lo: 1024 chunks of 16B each
    {
        const uint4* gh = (const uint4*)(g_Ahi + (size_t)rowBase * DD);
        const uint4* gl = (const uint4*)(g_Alo + (size_t)rowBase * DD);
#pragma unroll
        for (int it = 0; it < 4; it++) {
            int chunk = it * 256 + tid;          // 0..1023
            int r = chunk >> 4, c16 = chunk & 15;
            int dsw = (c16 ^ (r & 7));
            *(uint4*)(sA[0] + r * 256 + dsw * 16) = __ldg(&gh[chunk]);
            *(uint4*)(sA[1] + r * 256 + dsw * 16) = __ldg(&gl[chunk]);
        }
        if (tid < 128) sBias[tid] = __ldg(&bias[tid]);
    }
    __syncthreads();

    uint32_t aHiBase = smem_u32(sA[0]);
    uint32_t aLoBase = smem_u32(sA[1]);
    int wm = wid & 1, wn = wid >> 1;

    const __nv_bfloat16* Bh = g_Bhi + (size_t)layer * 256 * DD;
    const __nv_bfloat16* Bl = g_Blo + (size_t)layer * 256 * DD;

    float acc[2][8][4];
#pragma unroll
    for (int mt = 0; mt < 2; mt++)
#pragma unroll
        for (int nt = 0; nt < 8; nt++)
#pragma unroll
            for (int q = 0; q < 4; q++) acc[mt][nt][q] = 0.0f;

    // per-lane constant pieces
    int aRow = (lane & 15);            // + mtile base
    int aC16 = (lane >> 4);            // + kstep*2
    int bN = wn * 64 + (lane >> 2);    // + nt*8
    int bK = (lane & 3) * 2;           // + kstep*16 (+8 for reg 1)

#pragma unroll
    for (int ks = 0; ks < 8; ks++) {
        uint32_t ah[2][4], al[2][4];
#pragma unroll
        for (int mt = 0; mt < 2; mt++) {
            int r = wm * 32 + mt * 16 + aRow;
            int c16 = ks * 2 + aC16;
            uint32_t off = (uint32_t)(r * 256 + ((c16 ^ (r & 7)) << 4));
            ldmatrix_x4(ah[mt][0], ah[mt][1], ah[mt][2], ah[mt][3], aHiBase + off);
            ldmatrix_x4(al[mt][0], al[mt][1], al[mt][2], al[mt][3], aLoBase + off);
        }
        uint32_t bh[8][2], bl[8][2];
#pragma unroll
        for (int nt = 0; nt < 8; nt++) {
            size_t o = (size_t)(bN + nt * 8) * DD + ks * 16 + bK;
            bh[nt][0] = __ldg((const uint32_t*)(Bh + o));
            bh[nt][1] = __ldg((const uint32_t*)(Bh + o + 8));
            bl[nt][0] = __ldg((const uint32_t*)(Bl + o));
            bl[nt][1] = __ldg((const uint32_t*)(Bl + o + 8));
        }
#pragma unroll
        for (int mt = 0; mt < 2; mt++)
#pragma unroll
            for (int nt = 0; nt < 8; nt++) {
                mma_bf16(acc[mt][nt], ah[mt], bh[nt]);
                mma_bf16(acc[mt][nt], ah[mt], bl[nt]);
                mma_bf16(acc[mt][nt], al[mt], bh[nt]);
            }
    }

    // epilogue
#pragma unroll
    for (int mt = 0; mt < 2; mt++) {
        int r0 = rowBase + wm * 32 + mt * 16 + (lane >> 2);
#pragma unroll
        for (int nt = 0; nt < 8; nt++) {
            int col = wn * 64 + nt * 8 + (lane & 3) * 2;
            float2 v01 = make_float2(acc[mt][nt][0], acc[mt][nt][1]);
            float2 v23 = make_float2(acc[mt][nt][2], acc[mt][nt][3]);
            if (col >= 128) {
                v01.x += sBias[col - 128];     v01.y += sBias[col - 127];
                v23.x += sBias[col - 128];     v23.y += sBias[col - 127];
            }
            if (r0 < NN)     *(float2*)(g_Y + (size_t)r0 * 256 + col)       = v01;
            if (r0 + 8 < NN) *(float2*)(g_Y + (size_t)(r0 + 8) * 256 + col) = v23;
        }
    }
}

// ---------------- combine: gather-mean + self term (+ReLU) ----------------
// DST=0: fp32 to out.  DST=1: bf16 hi/lo row-major (next GEMM input).
template <int DST, bool RELU>
__global__ void __launch_bounds__(256) k_combine(float* __restrict__ outx) {
    int w = (blockIdx.x * blockDim.x + threadIdx.x) >> 5;
    int lane = threadIdx.x & 31;
    if (w >= NN) return;

    const float4* __restrict__ Y4 = (const float4*)g_Y;
    int base = g_rowptr[w];
    int cnt = g_deg[w];

    float4 acc = make_float4(0.f, 0.f, 0.f, 0.f);
    if (cnt > 0) {
        int jNext = __ldg(&g_col[base]);
#pragma unroll 1
        for (int tt = 0; tt < cnt - 1; tt++) {
            int j = jNext;
            jNext = __ldg(&g_col[base + tt + 1]);
            float4 v = __ldg(&Y4[(size_t)j * 64 + lane]);
            acc.x += v.x; acc.y += v.y; acc.z += v.z; acc.w += v.w;
        }
        float4 v = __ldg(&Y4[(size_t)jNext * 64 + lane]);
        acc.x += v.x; acc.y += v.y; acc.z += v.z; acc.w += v.w;
    }

    float di = g_deginv[w];
    float4 rr = __ldg(&Y4[(size_t)w * 64 + 32 + lane]);

    float4 o;
    o.x = fmaf(acc.x, di, rr.x);
    o.y = fmaf(acc.y, di, rr.y);
    o.z = fmaf(acc.z, di, rr.z);
    o.w = fmaf(acc.w, di, rr.w);
    if (RELU) {
        o.x = fmaxf(o.x, 0.f); o.y = fmaxf(o.y, 0.f);
        o.z = fmaxf(o.z, 0.f); o.w = fmaxf(o.w, 0.f);
    }

    if (DST == 0) {
        ((float4*)outx)[(size_t)w * 32 + lane] = o;
    } else {
        store_hilo_rm(g_Ahi, g_Alo, (size_t)w, lane * 4, o);
    }
}

// ---------------- launch ----------------
extern "C" void kernel_launch(void* const* d_in, const int* in_sizes, int n_in,
                              void* d_out, int out_size)
{
    const float* x  = nullptr;
    const void*  ei = nullptr;
    const float* Wm[6] = {nullptr, nullptr, nullptr, nullptr, nullptr, nullptr};
    const float* Bm[3] = {nullptr, nullptr, nullptr};
    int nw = 0, nb = 0;
    for (int i = 0; i < n_in; i++) {
        long long sz = in_sizes[i];
        if (sz == (long long)NN * DD)      x  = (const float*)d_in[i];
        else if (sz == (long long)2 * NE)  ei = d_in[i];
        else if (sz == (long long)NE)      { /* edge_attr, unused */ }
        else if (sz == DD * DD)            { if (nw < 6) Wm[nw++] = (const float*)d_in[i]; }
        else if (sz == DD)                 { if (nb < 3) Bm[nb++] = (const float*)d_in[i]; }
    }
    float* out = (float*)d_out;
    if (!x || !ei || nw < 6 || nb < 3) return;

    const int EB = (NE + 255) / 256;
    const int NB = (NN + 255) / 256;
    const int CB = (NN * 32 + 255) / 256;
    const int PA = (PADN * 32 + 255) / 256;
    const int PW = (3 * 256 * 32 + 255) / 256;

    // CSR build
    k_detect<<<1, 256>>>((const int*)ei);
    k_zero<<<NB, 256>>>();
    k_hist<<<EB, 256>>>(ei);
    k_scan_local<<<NSB, SCAN_B>>>();
    k_scan_off<<<1, 32>>>();
    k_scan_add<<<NSB, SCAN_B>>>();
    k_fill<<<EB, 256>>>(ei);

    // conversions
    k_prepA<<<PA, 256>>>(x);
    k_prepW<<<PW, 256>>>(Wm[0], Wm[1], Wm[2], Wm[3], Wm[4], Wm[5]);

    // layer 1
    k_gemm_mma<<<GRIDM, 256>>>(0, Bm[0]);
    k_combine<1, true><<<CB, 256>>>(out);
    // layer 2
    k_gemm_mma<<<GRIDM, 256>>>(1, Bm[1]);
    k_combine<1, true><<<CB, 256>>>(out);
    // layer 3
    k_gemm_mma<<<GRIDM, 256>>>(2, Bm[2]);
    k_combine<0, false><<<CB, 256>>>(out);
}

// round 8
// speedup vs baseline: 1.4466x; 1.0770x over previous
#include <cuda_runtime.h>
#include <cuda_bf16.h>
#include <cuda_fp16.h>
#include <cstdint>

// GraphSAGE 3-layer, mean aggregation — aggregate-first formulation.
// Per layer:  agg_i = deg_inv * sum_{j in N(i)} h_j          (fp16 gather, fp32 accum)
//             h'_i  = act( [agg_i | h_i] @ [Wl | Wr]^T + b ) (K=256 compensated-bf16 MMA)
// All device-global scratch referenced ONLY from device code (selector ints).
// Static shared memory only (<48KB). No cudaFuncSetAttribute / cudaGetSymbolAddress.

#define NN 100000
#define NE 1600000
#define DD 128
#define SCAN_B 1024
#define NSB 98
#define MTILE 32
#define GRIDM 3125                 // ceil(100000/32)

// ---------------- static device scratch ----------------
__device__ int   g_deg[NN];
__device__ int   g_fill[NN];
__device__ int   g_rowptr[NN];
__device__ float g_deginv[NN];
__device__ int   g_col[NE];
__device__ int   g_bsum[NSB];
__device__ int   g_is64;
__device__ __align__(16) float  g_agg[(size_t)NN * DD];
__device__ __align__(16) float  g_h32[(size_t)NN * DD];
__device__ __align__(16) __half g_h16[(size_t)NN * DD];
__device__ __align__(16) uint2  g_Bpk[3 * 128 * 128];   // [layer][n][k/2]: x={hi k,k+1}, y={lo k,k+1}

// ---------------- helpers ----------------
__device__ __forceinline__ uint32_t smem_u32(const void* p) {
    uint32_t a;
    asm("{ .reg .u64 t; cvta.to.shared.u64 t, %1; cvt.u32.u64 %0, t; }" : "=r"(a) : "l"(p));
    return a;
}
__device__ __forceinline__ void ldmatrix_x4(uint32_t& r0, uint32_t& r1, uint32_t& r2, uint32_t& r3, uint32_t addr) {
    asm volatile("ldmatrix.sync.aligned.m8n8.x4.shared.b16 {%0,%1,%2,%3}, [%4];"
                 : "=r"(r0), "=r"(r1), "=r"(r2), "=r"(r3) : "r"(addr));
}
__device__ __forceinline__ void mma_bf16(float* c, const uint32_t* a, const uint32_t* b) {
    asm volatile("mma.sync.aligned.m16n8k16.row.col.f32.bf16.bf16.f32 "
                 "{%0,%1,%2,%3}, {%4,%5,%6,%7}, {%8,%9}, {%0,%1,%2,%3};"
                 : "+f"(c[0]), "+f"(c[1]), "+f"(c[2]), "+f"(c[3])
                 : "r"(a[0]), "r"(a[1]), "r"(a[2]), "r"(a[3]), "r"(b[0]), "r"(b[1]));
}
__device__ __forceinline__ unsigned short f2bf(float f) {
    __nv_bfloat16 h = __float2bfloat16_rn(f);
    return *reinterpret_cast<unsigned short*>(&h);
}
__device__ __forceinline__ float bf2f(unsigned short u) {
    __nv_bfloat16 h = *reinterpret_cast<__nv_bfloat16*>(&u);
    return __bfloat162float(h);
}
__device__ __forceinline__ void split4(float4 v, uint2& uh, uint2& ul) {
    unsigned short hx = f2bf(v.x), hy = f2bf(v.y), hz = f2bf(v.z), hw = f2bf(v.w);
    uh = make_uint2((uint32_t)hx | ((uint32_t)hy << 16), (uint32_t)hz | ((uint32_t)hw << 16));
    unsigned short lx = f2bf(v.x - bf2f(hx)), ly = f2bf(v.y - bf2f(hy));
    unsigned short lz = f2bf(v.z - bf2f(hz)), lw = f2bf(v.w - bf2f(hw));
    ul = make_uint2((uint32_t)lx | ((uint32_t)ly << 16), (uint32_t)lz | ((uint32_t)lw << 16));
}

// ---------------- edge_index dtype detection ----------------
__global__ void k_detect(const int* __restrict__ ei32) {
    __shared__ int nz;
    if (threadIdx.x == 0) nz = 0;
    __syncthreads();
    int local = 0;
    for (int i = threadIdx.x; i < 4096; i += blockDim.x)
        if (ei32[2 * i + 1] != 0) local = 1;
    if (local) atomicOr(&nz, 1);
    __syncthreads();
    if (threadIdx.x == 0) g_is64 = (nz == 0) ? 1 : 0;
}
__device__ __forceinline__ int load_edge(const void* ei, int idx, int is64) {
    int v;
    if (is64) v = (int)((const long long*)ei)[idx];
    else      v = ((const int*)ei)[idx];
    v = v < 0 ? 0 : (v >= NN ? NN - 1 : v);
    return v;
}

// ---------------- CSR build ----------------
__global__ void k_zero() {
    int i = blockIdx.x * blockDim.x + threadIdx.x;
    if (i < NN) { g_deg[i] = 0; g_fill[i] = 0; }
}
__global__ void k_hist(const void* __restrict__ ei) {
    int e = blockIdx.x * blockDim.x + threadIdx.x;
    if (e < NE) atomicAdd(&g_deg[load_edge(ei, NE + e, g_is64)], 1);
}
__global__ void k_scan_local() {
    __shared__ int s[2][SCAN_B];
    int t = threadIdx.x, gid = blockIdx.x * SCAN_B + t;
    int v = (gid < NN) ? g_deg[gid] : 0;
    int cur = 0;
    s[0][t] = v;
    __syncthreads();
    for (int off = 1; off < SCAN_B; off <<= 1) {
        int add = (t >= off) ? s[cur][t - off] : 0;
        s[cur ^ 1][t] = s[cur][t] + add;
        cur ^= 1;
        __syncthreads();
    }
    int incl = s[cur][t];
    if (gid < NN) g_rowptr[gid] = incl - v;
    if (t == SCAN_B - 1) g_bsum[blockIdx.x] = incl;
}
__global__ void k_scan_off() {
    if (blockIdx.x == 0 && threadIdx.x == 0) {
        int run = 0;
        for (int b = 0; b < NSB; b++) { int tmp = g_bsum[b]; g_bsum[b] = run; run += tmp; }
    }
}
__global__ void k_scan_add() {
    int gid = blockIdx.x * SCAN_B + threadIdx.x;
    if (gid < NN) {
        g_rowptr[gid] += g_bsum[blockIdx.x];
        int d = g_deg[gid];
        g_deginv[gid] = 1.0f / (float)(d > 1 ? d : 1);
    }
}
__global__ void k_fill(const void* __restrict__ ei) {
    int e = blockIdx.x * blockDim.x + threadIdx.x;
    if (e < NE) {
        int is64 = g_is64;
        int d = load_edge(ei, NE + e, is64);
        int s = load_edge(ei, e, is64);
        int pos = g_rowptr[d] + atomicAdd(&g_fill[d], 1);
        g_col[pos] = s;
    }
}

// ---------------- prep: x -> fp16 copy (gather source for layer 1) ----------------
__global__ void k_prepA(const float* __restrict__ x) {
    int id = blockIdx.x * blockDim.x + threadIdx.x;      // NN*32
    if (id >= NN * 32) return;
    int row = id >> 5, k4 = id & 31;
    float4 v = __ldg((const float4*)(x + (size_t)row * DD) + k4);
    __half2 a = __floats2half2_rn(v.x, v.y);
    __half2 b = __floats2half2_rn(v.z, v.w);
    uint2 u = make_uint2(*(uint32_t*)&a, *(uint32_t*)&b);
    ((uint2*)g_h16)[(size_t)row * 32 + k4] = u;
}

// ---------------- prep: weights -> packed hi/lo B ([layer][n][K=256]) ----------------
__global__ void k_prepW(const float* __restrict__ W1l, const float* __restrict__ W1r,
                        const float* __restrict__ W2l, const float* __restrict__ W2r,
                        const float* __restrict__ W3l, const float* __restrict__ W3r) {
    int id = blockIdx.x * blockDim.x + threadIdx.x;      // 3*128*64
    if (id >= 3 * 128 * 64) return;
    int layer = id >> 13;
    int rem = id & 8191;
    int n = rem >> 6, kq = rem & 63;
    int k = kq * 4;
    const float* Wl = layer == 0 ? W1l : (layer == 1 ? W2l : W3l);
    const float* Wr = layer == 0 ? W1r : (layer == 1 ? W2r : W3r);
    float4 v = (k < 128) ? __ldg((const float4*)(Wl + n * DD + k))
                         : __ldg((const float4*)(Wr + n * DD + (k - 128)));
    unsigned short h0 = f2bf(v.x), h1 = f2bf(v.y), h2 = f2bf(v.z), h3 = f2bf(v.w);
    unsigned short l0 = f2bf(v.x - bf2f(h0)), l1 = f2bf(v.y - bf2f(h1));
    unsigned short l2 = f2bf(v.z - bf2f(h2)), l3 = f2bf(v.w - bf2f(h3));
    uint2* dst = g_Bpk + (size_t)layer * 128 * 128 + n * 128 + (k >> 1);
    dst[0] = make_uint2((uint32_t)h0 | ((uint32_t)h1 << 16), (uint32_t)l0 | ((uint32_t)l1 << 16));
    dst[1] = make_uint2((uint32_t)h2 | ((uint32_t)h3 << 16), (uint32_t)l2 | ((uint32_t)l3 << 16));
}

// ---------------- aggregate: agg_i = deg_inv * sum h16_j  (warp per node, MLP=4) ----------------
__global__ void __launch_bounds__(256) k_agg() {
    int w = blockIdx.x * 8 + (threadIdx.x >> 5);
    int lane = threadIdx.x & 31;
    if (w >= NN) return;

    const uint2* __restrict__ H = (const uint2*)g_h16;   // row = 32 uint2 (128 fp16)
    int base = g_rowptr[w];
    int cnt = g_deg[w];

    float4 acc = make_float4(0.f, 0.f, 0.f, 0.f);
    int t = 0;
    for (; t + 4 <= cnt; t += 4) {
        int j0 = __ldg(&g_col[base + t]);
        int j1 = __ldg(&g_col[base + t + 1]);
        int j2 = __ldg(&g_col[base + t + 2]);
        int j3 = __ldg(&g_col[base + t + 3]);
        uint2 u0 = __ldg(&H[(size_t)j0 * 32 + lane]);
        uint2 u1 = __ldg(&H[(size_t)j1 * 32 + lane]);
        uint2 u2 = __ldg(&H[(size_t)j2 * 32 + lane]);
        uint2 u3 = __ldg(&H[(size_t)j3 * 32 + lane]);
#define ACC(u) { float2 f0 = __half22float2(*(__half2*)&(u).x); \
                 float2 f1 = __half22float2(*(__half2*)&(u).y); \
                 acc.x += f0.x; acc.y += f0.y; acc.z += f1.x; acc.w += f1.y; }
        ACC(u0) ACC(u1) ACC(u2) ACC(u3)
    }
    for (; t < cnt; t++) {
        int j = __ldg(&g_col[base + t]);
        uint2 u = __ldg(&H[(size_t)j * 32 + lane]);
        ACC(u)
    }
#undef ACC
    float di = g_deginv[w];
    float4 o = make_float4(acc.x * di, acc.y * di, acc.z * di, acc.w * di);
    ((float4*)g_agg)[(size_t)w * 32 + lane] = o;
}

// ---------------- GEMM: h' = act([agg|h] @ Bext^T + b), K=256, N=128, MTILE=32 ----------------
// 8 warps: wm = wid&1 (16-row group), wn = wid>>1 (32-col group); warp tile 16x32.
__global__ void __launch_bounds__(256) k_gemm_mma(
    const float* __restrict__ xin, int srcSel, int layer,
    const float* __restrict__ bias, float* __restrict__ outp, int last)
{
    __shared__ __align__(16) unsigned char sAhi[32 * 512];   // 16 KB
    __shared__ __align__(16) unsigned char sAlo[32 * 512];   // 16 KB
    __shared__ float sBias[128];

    int tid = threadIdx.x, wid = tid >> 5, lane = tid & 31;
    int rowBase = blockIdx.x * MTILE;
    const float* hsrc = srcSel == 0 ? xin : g_h32;

    // stage A_ext = [agg | h] (32 x 256 fp32) -> bf16 hi/lo, swizzled 512B rows
    {
        const float4* aggS = (const float4*)g_agg + (size_t)rowBase * 32;
        const float4* hS   = (const float4*)hsrc + (size_t)rowBase * 32;
#pragma unroll 1
        for (int it = 0; it < 8; it++) {
            int idx = it * 256 + tid;            // 0..2047
            int r = idx >> 6, q = idx & 63;      // row, quad (4 floats)
            int grow = rowBase + r;
            float4 v = make_float4(0.f, 0.f, 0.f, 0.f);
            if (grow < NN) v = (q < 32) ? __ldg(&aggS[r * 32 + q]) : __ldg(&hS[r * 32 + (q - 32)]);
            uint2 uh, ul;
            split4(v, uh, ul);
            int c16 = q >> 1, half = q & 1;
            uint32_t off = (uint32_t)(r * 512 + ((c16 ^ (r & 7)) << 4) + half * 8);
            *(uint2*)(sAhi + off) = uh;
            *(uint2*)(sAlo + off) = ul;
        }
        if (tid < 128) sBias[tid] = __ldg(&bias[tid]);
    }
    __syncthreads();

    uint32_t aHiBase = smem_u32(sAhi);
    uint32_t aLoBase = smem_u32(sAlo);
    int wm = wid & 1, wn = wid >> 1;
    const uint2* __restrict__ Bpk = g_Bpk + (size_t)layer * 128 * 128;

    float acc[4][4];
#pragma unroll
    for (int nt = 0; nt < 4; nt++)
#pragma unroll
        for (int q = 0; q < 4; q++) acc[nt][q] = 0.0f;

#pragma unroll
    for (int ks = 0; ks < 16; ks++) {
        uint32_t ah[4], al[4];
        {
            int r = wm * 16 + (lane & 15);
            int c16 = ks * 2 + (lane >> 4);
            uint32_t off = (uint32_t)(r * 512 + ((c16 ^ (r & 7)) << 4));
            ldmatrix_x4(ah[0], ah[1], ah[2], ah[3], aHiBase + off);
            ldmatrix_x4(al[0], al[1], al[2], al[3], aLoBase + off);
        }
        uint32_t bh[4][2], bl[4][2];
#pragma unroll
        for (int nt = 0; nt < 4; nt++) {
            int n = wn * 32 + nt * 8 + (lane >> 2);
            int kb = ks * 16 + (lane & 3) * 2;
            uint2 p0 = __ldg(&Bpk[n * 128 + (kb >> 1)]);
            uint2 p1 = __ldg(&Bpk[n * 128 + ((kb + 8) >> 1)]);
            bh[nt][0] = p0.x; bh[nt][1] = p1.x;
            bl[nt][0] = p0.y; bl[nt][1] = p1.y;
        }
#pragma unroll
        for (int nt = 0; nt < 4; nt++) {
            mma_bf16(acc[nt], ah, bh[nt]);
            mma_bf16(acc[nt], ah, bl[nt]);
            mma_bf16(acc[nt], al, bh[nt]);
        }
    }

    // epilogue: +bias, (ReLU), write h32+h16 (or out if last)
    int r0 = rowBase + wm * 16 + (lane >> 2);
#pragma unroll
    for (int nt = 0; nt < 4; nt++) {
        int col = wn * 32 + nt * 8 + (lane & 3) * 2;
        float b0 = sBias[col], b1 = sBias[col + 1];
        float2 v01 = make_float2(acc[nt][0] + b0, acc[nt][1] + b1);
        float2 v23 = make_float2(acc[nt][2] + b0, acc[nt][3] + b1);
        if (!last) {
            v01.x = fmaxf(v01.x, 0.f); v01.y = fmaxf(v01.y, 0.f);
            v23.x = fmaxf(v23.x, 0.f); v23.y = fmaxf(v23.y, 0.f);
        }
        if (last) {
            if (r0 < NN)     *(float2*)(outp + (size_t)r0 * DD + col)       = v01;
            if (r0 + 8 < NN) *(float2*)(outp + (size_t)(r0 + 8) * DD + col) = v23;
        } else {
            if (r0 < NN) {
                *(float2*)(g_h32 + (size_t)r0 * DD + col) = v01;
                __half2 hh = __floats2half2_rn(v01.x, v01.y);
                *(__half2*)(g_h16 + (size_t)r0 * DD + col) = hh;
            }
            if (r0 + 8 < NN) {
                *(float2*)(g_h32 + (size_t)(r0 + 8) * DD + col) = v23;
                __half2 hh = __floats2half2_rn(v23.x, v23.y);
                *(__half2*)(g_h16 + (size_t)(r0 + 8) * DD + col) = hh;
            }
        }
    }
}

// ---------------- launch ----------------
extern "C" void kernel_launch(void* const* d_in, const int* in_sizes, int n_in,
                              void* d_out, int out_size)
{
    const float* x  = nullptr;
    const void*  ei = nullptr;
    const float* Wm[6] = {nullptr, nullptr, nullptr, nullptr, nullptr, nullptr};
    const float* Bm[3] = {nullptr, nullptr, nullptr};
    int nw = 0, nb = 0;
    for (int i = 0; i < n_in; i++) {
        long long sz = in_sizes[i];
        if (sz == (long long)NN * DD)      x  = (const float*)d_in[i];
        else if (sz == (long long)2 * NE)  ei = d_in[i];
        else if (sz == (long long)NE)      { /* edge_attr, unused */ }
        else if (sz == DD * DD)            { if (nw < 6) Wm[nw++] = (const float*)d_in[i]; }
        else if (sz == DD)                 { if (nb < 3) Bm[nb++] = (const float*)d_in[i]; }
    }
    float* out = (float*)d_out;
    if (!x || !ei || nw < 6 || nb < 3) return;

    const int EB = (NE + 255) / 256;
    const int NB = (NN + 255) / 256;
    const int AB = (NN + 7) / 8;
    const int PA = (NN * 32 + 255) / 256;
    const int PW = (3 * 128 * 64 + 255) / 256;

    // CSR build
    k_detect<<<1, 256>>>((const int*)ei);
    k_zero<<<NB, 256>>>();
    k_hist<<<EB, 256>>>(ei);
    k_scan_local<<<NSB, SCAN_B>>>();
    k_scan_off<<<1, 32>>>();
    k_scan_add<<<NSB, SCAN_B>>>();
    k_fill<<<EB, 256>>>(ei);

    // prep
    k_prepA<<<PA, 256>>>(x);
    k_prepW<<<PW, 256>>>(Wm[0], Wm[1], Wm[2], Wm[3], Wm[4], Wm[5]);

    // layer 1: agg over x16 ; gemm([agg|x]) -> h32,h16
    k_agg<<<AB, 256>>>();
    k_gemm_mma<<<GRIDM, 256>>>(x, 0, 0, Bm[0], nullptr, 0);
    // layer 2
    k_agg<<<AB, 256>>>();
    k_gemm_mma<<<GRIDM, 256>>>(x, 1, 1, Bm[1], nullptr, 0);
    // layer 3 -> out
    k_agg<<<AB, 256>>>();
    k_gemm_mma<<<GRIDM, 256>>>(x, 1, 2, Bm[2], out, 1);
}

// round 9
// speedup vs baseline: 1.6440x; 1.1364x over previous
#include <cuda_runtime.h>
#include <cuda_bf16.h>
#include <cuda_fp16.h>
#include <cstdint>

// GraphSAGE 3-layer, mean aggregation — aggregate-first formulation.
// Per layer:  agg_i = deg_inv * sum_{j in N(i)} h_j          (fp16 gather, fp32 accum)
//             h'_i  = act( [agg_i | h_i] @ [Wl | Wr]^T + b ) (K=256 compensated-bf16 MMA)
// h kept ONLY as fp16 between layers (gather source + GEMM self half).
// Static shared memory only; device globals referenced only from device code.

#define NN 100000
#define NE 1600000
#define DD 128
#define SCAN_B 1024
#define NSB 98
#define MTILE 32
#define GRIDM 3125                 // ceil(100000/32)

// ---------------- static device scratch ----------------
__device__ int   g_deg[NN];
__device__ int   g_fill[NN];
__device__ int   g_rowptr[NN];
__device__ float g_deginv[NN];
__device__ int   g_col[NE];
__device__ int   g_bsum[NSB];
__device__ int   g_is64;
__device__ __align__(16) float  g_agg[(size_t)NN * DD];
__device__ __align__(16) __half g_h16[(size_t)NN * DD];
__device__ __align__(16) uint2  g_Bpk[3 * 128 * 128];   // [layer][n][k/2]: x={hi k,k+1}, y={lo k,k+1}

// ---------------- helpers ----------------
__device__ __forceinline__ uint32_t smem_u32(const void* p) {
    uint32_t a;
    asm("{ .reg .u64 t; cvta.to.shared.u64 t, %1; cvt.u32.u64 %0, t; }" : "=r"(a) : "l"(p));
    return a;
}
__device__ __forceinline__ void ldmatrix_x4(uint32_t& r0, uint32_t& r1, uint32_t& r2, uint32_t& r3, uint32_t addr) {
    asm volatile("ldmatrix.sync.aligned.m8n8.x4.shared.b16 {%0,%1,%2,%3}, [%4];"
                 : "=r"(r0), "=r"(r1), "=r"(r2), "=r"(r3) : "r"(addr));
}
__device__ __forceinline__ void mma_bf16(float* c, const uint32_t* a, const uint32_t* b) {
    asm volatile("mma.sync.aligned.m16n8k16.row.col.f32.bf16.bf16.f32 "
                 "{%0,%1,%2,%3}, {%4,%5,%6,%7}, {%8,%9}, {%0,%1,%2,%3};"
                 : "+f"(c[0]), "+f"(c[1]), "+f"(c[2]), "+f"(c[3])
                 : "r"(a[0]), "r"(a[1]), "r"(a[2]), "r"(a[3]), "r"(b[0]), "r"(b[1]));
}
__device__ __forceinline__ unsigned short f2bf(float f) {
    __nv_bfloat16 h = __float2bfloat16_rn(f);
    return *reinterpret_cast<unsigned short*>(&h);
}
__device__ __forceinline__ float bf2f(unsigned short u) {
    __nv_bfloat16 h = *reinterpret_cast<__nv_bfloat16*>(&u);
    return __bfloat162float(h);
}
__device__ __forceinline__ void split4(float4 v, uint2& uh, uint2& ul) {
    unsigned short hx = f2bf(v.x), hy = f2bf(v.y), hz = f2bf(v.z), hw = f2bf(v.w);
    uh = make_uint2((uint32_t)hx | ((uint32_t)hy << 16), (uint32_t)hz | ((uint32_t)hw << 16));
    unsigned short lx = f2bf(v.x - bf2f(hx)), ly = f2bf(v.y - bf2f(hy));
    unsigned short lz = f2bf(v.z - bf2f(hz)), lw = f2bf(v.w - bf2f(hw));
    ul = make_uint2((uint32_t)lx | ((uint32_t)ly << 16), (uint32_t)lz | ((uint32_t)lw << 16));
}
// 2 packed fp16 -> packed bf16 hi + packed bf16 lo
__device__ __forceinline__ void h2_to_bf(uint32_t u, uint32_t& hi, uint32_t& lo) {
    float2 f = __half22float2(*(__half2*)&u);
    unsigned short h0 = f2bf(f.x), h1 = f2bf(f.y);
    unsigned short l0 = f2bf(f.x - bf2f(h0)), l1 = f2bf(f.y - bf2f(h1));
    hi = (uint32_t)h0 | ((uint32_t)h1 << 16);
    lo = (uint32_t)l0 | ((uint32_t)l1 << 16);
}

// ---------------- edge_index dtype detection ----------------
__global__ void k_detect(const int* __restrict__ ei32) {
    __shared__ int nz;
    if (threadIdx.x == 0) nz = 0;
    __syncthreads();
    int local = 0;
    for (int i = threadIdx.x; i < 4096; i += blockDim.x)
        if (ei32[2 * i + 1] != 0) local = 1;
    if (local) atomicOr(&nz, 1);
    __syncthreads();
    if (threadIdx.x == 0) g_is64 = (nz == 0) ? 1 : 0;
}
__device__ __forceinline__ int load_edge(const void* ei, int idx, int is64) {
    int v;
    if (is64) v = (int)((const long long*)ei)[idx];
    else      v = ((const int*)ei)[idx];
    v = v < 0 ? 0 : (v >= NN ? NN - 1 : v);
    return v;
}

// ---------------- CSR build ----------------
__global__ void k_zero() {
    int i = blockIdx.x * blockDim.x + threadIdx.x;
    if (i < NN) { g_deg[i] = 0; g_fill[i] = 0; }
}
__global__ void k_hist(const void* __restrict__ ei) {
    int e = blockIdx.x * blockDim.x + threadIdx.x;
    if (e < NE) atomicAdd(&g_deg[load_edge(ei, NE + e, g_is64)], 1);
}
__global__ void k_scan_local() {
    __shared__ int s[2][SCAN_B];
    int t = threadIdx.x, gid = blockIdx.x * SCAN_B + t;
    int v = (gid < NN) ? g_deg[gid] : 0;
    int cur = 0;
    s[0][t] = v;
    __syncthreads();
    for (int off = 1; off < SCAN_B; off <<= 1) {
        int add = (t >= off) ? s[cur][t - off] : 0;
        s[cur ^ 1][t] = s[cur][t] + add;
        cur ^= 1;
        __syncthreads();
    }
    int incl = s[cur][t];
    if (gid < NN) g_rowptr[gid] = incl - v;
    if (t == SCAN_B - 1) g_bsum[blockIdx.x] = incl;
}
__global__ void k_scan_off() {
    if (blockIdx.x == 0 && threadIdx.x == 0) {
        int run = 0;
        for (int b = 0; b < NSB; b++) { int tmp = g_bsum[b]; g_bsum[b] = run; run += tmp; }
    }
}
__global__ void k_scan_add() {
    int gid = blockIdx.x * SCAN_B + threadIdx.x;
    if (gid < NN) {
        g_rowptr[gid] += g_bsum[blockIdx.x];
        int d = g_deg[gid];
        g_deginv[gid] = 1.0f / (float)(d > 1 ? d : 1);
    }
}
__global__ void k_fill(const void* __restrict__ ei) {
    int e = blockIdx.x * blockDim.x + threadIdx.x;
    if (e < NE) {
        int is64 = g_is64;
        int d = load_edge(ei, NE + e, is64);
        int s = load_edge(ei, e, is64);
        int pos = g_rowptr[d] + atomicAdd(&g_fill[d], 1);
        g_col[pos] = s;
    }
}

// ---------------- prep: x -> fp16 h (layer-1 state) ----------------
__global__ void k_prepA(const float* __restrict__ x) {
    int id = blockIdx.x * blockDim.x + threadIdx.x;      // NN*32
    if (id >= NN * 32) return;
    int row = id >> 5, k4 = id & 31;
    float4 v = __ldg((const float4*)(x + (size_t)row * DD) + k4);
    __half2 a = __floats2half2_rn(v.x, v.y);
    __half2 b = __floats2half2_rn(v.z, v.w);
    uint2 u = make_uint2(*(uint32_t*)&a, *(uint32_t*)&b);
    ((uint2*)g_h16)[(size_t)row * 32 + k4] = u;
}

// ---------------- prep: weights -> packed hi/lo B ([layer][n][K=256]) ----------------
__global__ void k_prepW(const float* __restrict__ W1l, const float* __restrict__ W1r,
                        const float* __restrict__ W2l, const float* __restrict__ W2r,
                        const float* __restrict__ W3l, const float* __restrict__ W3r) {
    int id = blockIdx.x * blockDim.x + threadIdx.x;      // 3*128*64
    if (id >= 3 * 128 * 64) return;
    int layer = id >> 13;
    int rem = id & 8191;
    int n = rem >> 6, kq = rem & 63;
    int k = kq * 4;
    const float* Wl = layer == 0 ? W1l : (layer == 1 ? W2l : W3l);
    const float* Wr = layer == 0 ? W1r : (layer == 1 ? W2r : W3r);
    float4 v = (k < 128) ? __ldg((const float4*)(Wl + n * DD + k))
                         : __ldg((const float4*)(Wr + n * DD + (k - 128)));
    unsigned short h0 = f2bf(v.x), h1 = f2bf(v.y), h2 = f2bf(v.z), h3 = f2bf(v.w);
    unsigned short l0 = f2bf(v.x - bf2f(h0)), l1 = f2bf(v.y - bf2f(h1));
    unsigned short l2 = f2bf(v.z - bf2f(h2)), l3 = f2bf(v.w - bf2f(h3));
    uint2* dst = g_Bpk + (size_t)layer * 128 * 128 + n * 128 + (k >> 1);
    dst[0] = make_uint2((uint32_t)h0 | ((uint32_t)h1 << 16), (uint32_t)l0 | ((uint32_t)l1 << 16));
    dst[1] = make_uint2((uint32_t)h2 | ((uint32_t)h3 << 16), (uint32_t)l2 | ((uint32_t)l3 << 16));
}

// ---------------- aggregate: agg_i = deg_inv * sum h16_j  (warp per node, MLP=8) ----------------
__global__ void __launch_bounds__(256) k_agg() {
    int w = blockIdx.x * 8 + (threadIdx.x >> 5);
    int lane = threadIdx.x & 31;
    if (w >= NN) return;

    const uint2* __restrict__ H = (const uint2*)g_h16;   // row = 32 uint2 (128 fp16)
    int base = g_rowptr[w];
    int cnt = g_deg[w];

    float4 acc = make_float4(0.f, 0.f, 0.f, 0.f);
#define ACC(u) { float2 f0 = __half22float2(*(__half2*)&(u).x); \
                 float2 f1 = __half22float2(*(__half2*)&(u).y); \
                 acc.x += f0.x; acc.y += f0.y; acc.z += f1.x; acc.w += f1.y; }
    int t = 0;
    for (; t + 8 <= cnt; t += 8) {
        int j[8];
#pragma unroll
        for (int q = 0; q < 8; q++) j[q] = __ldg(&g_col[base + t + q]);
        uint2 u[8];
#pragma unroll
        for (int q = 0; q < 8; q++) u[q] = __ldg(&H[(size_t)j[q] * 32 + lane]);
#pragma unroll
        for (int q = 0; q < 8; q++) ACC(u[q])
    }
    if (t + 4 <= cnt) {
        int j[4];
#pragma unroll
        for (int q = 0; q < 4; q++) j[q] = __ldg(&g_col[base + t + q]);
        uint2 u[4];
#pragma unroll
        for (int q = 0; q < 4; q++) u[q] = __ldg(&H[(size_t)j[q] * 32 + lane]);
#pragma unroll
        for (int q = 0; q < 4; q++) ACC(u[q])
        t += 4;
    }
    for (; t < cnt; t++) {
        int j = __ldg(&g_col[base + t]);
        uint2 u = __ldg(&H[(size_t)j * 32 + lane]);
        ACC(u)
    }
#undef ACC
    float di = g_deginv[w];
    float4 o = make_float4(acc.x * di, acc.y * di, acc.z * di, acc.w * di);
    ((float4*)g_agg)[(size_t)w * 32 + lane] = o;
}

// ---------------- GEMM: h' = act([agg|h16] @ Bext^T + b), K=256, N=128, MTILE=32 ----------------
// 8 warps: wm = wid&1 (16-row group), wn = wid>>1 (32-col group); warp tile 16x32.
__global__ void __launch_bounds__(256) k_gemm_mma(
    int layer, const float* __restrict__ bias, float* __restrict__ outp, int last)
{
    __shared__ __align__(16) unsigned char sAhi[32 * 512];   // 16 KB
    __shared__ __align__(16) unsigned char sAlo[32 * 512];   // 16 KB
    __shared__ float sBias[128];

    int tid = threadIdx.x, wid = tid >> 5, lane = tid & 31;
    int rowBase = blockIdx.x * MTILE;

    // ---- stage A_ext = [agg(fp32) | h16] -> bf16 hi/lo, swizzled 512B rows; all loads unrolled ----
    {
        const float4* aggS = (const float4*)g_agg + (size_t)rowBase * 32;
        const uint4*  hS   = (const uint4*)g_h16 + (size_t)rowBase * 16;   // 16 uint4/row
        float4 av[4];
        uint4  hv[2];
#pragma unroll
        for (int it = 0; it < 4; it++) {
            int idx = it * 256 + tid;
            int r = idx >> 5, q = idx & 31;
            av[it] = (rowBase + r < NN) ? __ldg(&aggS[r * 32 + q]) : make_float4(0.f, 0.f, 0.f, 0.f);
        }
#pragma unroll
        for (int it = 0; it < 2; it++) {
            int idx = it * 256 + tid;
            int r = idx >> 4, u = idx & 15;
            hv[it] = (rowBase + r < NN) ? __ldg(&hS[r * 16 + u]) : make_uint4(0u, 0u, 0u, 0u);
        }
#pragma unroll
        for (int it = 0; it < 4; it++) {
            int idx = it * 256 + tid;
            int r = idx >> 5, q = idx & 31;
            uint2 uh, ul;
            split4(av[it], uh, ul);
            int c16 = q >> 1, half = q & 1;
            uint32_t off = (uint32_t)(r * 512 + ((c16 ^ (r & 7)) << 4) + half * 8);
            *(uint2*)(sAhi + off) = uh;
            *(uint2*)(sAlo + off) = ul;
        }
#pragma unroll
        for (int it = 0; it < 2; it++) {
            int idx = it * 256 + tid;
            int r = idx >> 4, u = idx & 15;
            uint4 H, L;
            h2_to_bf(hv[it].x, H.x, L.x);
            h2_to_bf(hv[it].y, H.y, L.y);
            h2_to_bf(hv[it].z, H.z, L.z);
            h2_to_bf(hv[it].w, H.w, L.w);
            int c16 = 16 + u;
            uint32_t off = (uint32_t)(r * 512 + ((c16 ^ (r & 7)) << 4));
            *(uint4*)(sAhi + off) = H;
            *(uint4*)(sAlo + off) = L;
        }
        if (tid < 128) sBias[tid] = __ldg(&bias[tid]);
    }
    __syncthreads();

    uint32_t aHiBase = smem_u32(sAhi);
    uint32_t aLoBase = smem_u32(sAlo);
    int wm = wid & 1, wn = wid >> 1;
    const uint2* __restrict__ Bpk = g_Bpk + (size_t)layer * 128 * 128;

    float acc[4][4];
#pragma unroll
    for (int nt = 0; nt < 4; nt++)
#pragma unroll
        for (int q = 0; q < 4; q++) acc[nt][q] = 0.0f;

#pragma unroll
    for (int ks = 0; ks < 16; ks++) {
        uint32_t ah[4], al[4];
        {
            int r = wm * 16 + (lane & 15);
            int c16 = ks * 2 + (lane >> 4);
            uint32_t off = (uint32_t)(r * 512 + ((c16 ^ (r & 7)) << 4));
            ldmatrix_x4(ah[0], ah[1], ah[2], ah[3], aHiBase + off);
            ldmatrix_x4(al[0], al[1], al[2], al[3], aLoBase + off);
        }
        uint32_t bh[4][2], bl[4][2];
#pragma unroll
        for (int nt = 0; nt < 4; nt++) {
            int n = wn * 32 + nt * 8 + (lane >> 2);
            int kb = ks * 16 + (lane & 3) * 2;
            uint2 p0 = __ldg(&Bpk[n * 128 + (kb >> 1)]);
            uint2 p1 = __ldg(&Bpk[n * 128 + ((kb + 8) >> 1)]);
            bh[nt][0] = p0.x; bh[nt][1] = p1.x;
            bl[nt][0] = p0.y; bl[nt][1] = p1.y;
        }
#pragma unroll
        for (int nt = 0; nt < 4; nt++) {
            mma_bf16(acc[nt], ah, bh[nt]);
            mma_bf16(acc[nt], ah, bl[nt]);
            mma_bf16(acc[nt], al, bh[nt]);
        }
    }

    // ---- epilogue: +bias, (ReLU), write h16 (or fp32 out if last) ----
    int r0 = rowBase + wm * 16 + (lane >> 2);
#pragma unroll
    for (int nt = 0; nt < 4; nt++) {
        int col = wn * 32 + nt * 8 + (lane & 3) * 2;
        float b0 = sBias[col], b1 = sBias[col + 1];
        float2 v01 = make_float2(acc[nt][0] + b0, acc[nt][1] + b1);
        float2 v23 = make_float2(acc[nt][2] + b0, acc[nt][3] + b1);
        if (!last) {
            v01.x = fmaxf(v01.x, 0.f); v01.y = fmaxf(v01.y, 0.f);
            v23.x = fmaxf(v23.x, 0.f); v23.y = fmaxf(v23.y, 0.f);
        }
        if (last) {
            if (r0 < NN)     *(float2*)(outp + (size_t)r0 * DD + col)       = v01;
            if (r0 + 8 < NN) *(float2*)(outp + (size_t)(r0 + 8) * DD + col) = v23;
        } else {
            if (r0 < NN) {
                __half2 hh = __floats2half2_rn(v01.x, v01.y);
                *(__half2*)(g_h16 + (size_t)r0 * DD + col) = hh;
            }
            if (r0 + 8 < NN) {
                __half2 hh = __floats2half2_rn(v23.x, v23.y);
                *(__half2*)(g_h16 + (size_t)(r0 + 8) * DD + col) = hh;
            }
        }
    }
}

// ---------------- launch ----------------
extern "C" void kernel_launch(void* const* d_in, const int* in_sizes, int n_in,
                              void* d_out, int out_size)
{
    const float* x  = nullptr;
    const void*  ei = nullptr;
    const float* Wm[6] = {nullptr, nullptr, nullptr, nullptr, nullptr, nullptr};
    const float* Bm[3] = {nullptr, nullptr, nullptr};
    int nw = 0, nb = 0;
    for (int i = 0; i < n_in; i++) {
        long long sz = in_sizes[i];
        if (sz == (long long)NN * DD)      x  = (const float*)d_in[i];
        else if (sz == (long long)2 * NE)  ei = d_in[i];
        else if (sz == (long long)NE)      { /* edge_attr, unused */ }
        else if (sz == DD * DD)            { if (nw < 6) Wm[nw++] = (const float*)d_in[i]; }
        else if (sz == DD)                 { if (nb < 3) Bm[nb++] = (const float*)d_in[i]; }
    }
    float* out = (float*)d_out;
    if (!x || !ei || nw < 6 || nb < 3) return;

    const int EB = (NE + 255) / 256;
    const int NB = (NN + 255) / 256;
    const int AB = (NN + 7) / 8;
    const int PA = (NN * 32 + 255) / 256;
    const int PW = (3 * 128 * 64 + 255) / 256;

    // CSR build
    k_detect<<<1, 256>>>((const int*)ei);
    k_zero<<<NB, 256>>>();
    k_hist<<<EB, 256>>>(ei);
    k_scan_local<<<NSB, SCAN_B>>>();
    k_scan_off<<<1, 32>>>();
    k_scan_add<<<NSB, SCAN_B>>>();
    k_fill<<<EB, 256>>>(ei);

    // prep
    k_prepA<<<PA, 256>>>(x);
    k_prepW<<<PW, 256>>>(Wm[0], Wm[1], Wm[2], Wm[3], Wm[4], Wm[5]);

    // layer 1
    k_agg<<<AB, 256>>>();
    k_gemm_mma<<<GRIDM, 256>>>(0, Bm[0], nullptr, 0);
    // layer 2
    k_agg<<<AB, 256>>>();
    k_gemm_mma<<<GRIDM, 256>>>(1, Bm[1], nullptr, 0);
    // layer 3 -> out
    k_agg<<<AB, 256>>>();
    k_gemm_mma<<<GRIDM, 256>>>(2, Bm[2], out, 1);
}

// round 12
// speedup vs baseline: 1.7351x; 1.0554x over previous
#include <cuda_runtime.h>
#include <cuda_bf16.h>
#include <cuda_fp16.h>
#include <cstdint>

// GraphSAGE 3-layer, mean aggregation — fused layer kernel with double-buffered state.
// Per layer (one kernel): per block of 32 nodes,
//   warp-gather: agg_i = deg_inv * sum_{j in N(i)} h16[cur]_j  (fp32 accum, bf16 hi/lo to smem)
//   MMA:         h16[1-cur]_i = act( [agg_i | h16[cur]_i] @ [Wl | Wr]^T + b )
// Double buffer removes the cross-block RAW hazard fusion created (R11 bug).

#define NN 100000
#define NE 1600000
#define DD 128
#define SCAN_B 1024
#define NSB 98
#define MTILE 32
#define GRIDM 3125                 // 3125*32 == 100000 exactly

// ---------------- static device scratch ----------------
__device__ int   g_deg[NN];
__device__ int   g_fill[NN];
__device__ int   g_rowptr[NN];
__device__ float g_deginv[NN];
__device__ int   g_col[NE];
__device__ int   g_bsum[NSB];
__device__ int   g_is64;
__device__ __align__(16) __half g_hA[(size_t)NN * DD];
__device__ __align__(16) __half g_hB[(size_t)NN * DD];
__device__ __align__(16) uint2  g_Bpk[3 * 128 * 128];   // [layer][n][k/2]: x={hi k,k+1}, y={lo k,k+1}

// ---------------- helpers ----------------
__device__ __forceinline__ uint32_t smem_u32(const void* p) {
    uint32_t a;
    asm("{ .reg .u64 t; cvta.to.shared.u64 t, %1; cvt.u32.u64 %0, t; }" : "=r"(a) : "l"(p));
    return a;
}
__device__ __forceinline__ void ldmatrix_x4(uint32_t& r0, uint32_t& r1, uint32_t& r2, uint32_t& r3, uint32_t addr) {
    asm volatile("ldmatrix.sync.aligned.m8n8.x4.shared.b16 {%0,%1,%2,%3}, [%4];"
                 : "=r"(r0), "=r"(r1), "=r"(r2), "=r"(r3) : "r"(addr));
}
__device__ __forceinline__ void mma_bf16(float* c, const uint32_t* a, const uint32_t* b) {
    asm volatile("mma.sync.aligned.m16n8k16.row.col.f32.bf16.bf16.f32 "
                 "{%0,%1,%2,%3}, {%4,%5,%6,%7}, {%8,%9}, {%0,%1,%2,%3};"
                 : "+f"(c[0]), "+f"(c[1]), "+f"(c[2]), "+f"(c[3])
                 : "r"(a[0]), "r"(a[1]), "r"(a[2]), "r"(a[3]), "r"(b[0]), "r"(b[1]));
}
__device__ __forceinline__ unsigned short f2bf(float f) {
    __nv_bfloat16 h = __float2bfloat16_rn(f);
    return *reinterpret_cast<unsigned short*>(&h);
}
__device__ __forceinline__ float bf2f(unsigned short u) {
    __nv_bfloat16 h = *reinterpret_cast<__nv_bfloat16*>(&u);
    return __bfloat162float(h);
}
__device__ __forceinline__ void split4(float4 v, uint2& uh, uint2& ul) {
    unsigned short hx = f2bf(v.x), hy = f2bf(v.y), hz = f2bf(v.z), hw = f2bf(v.w);
    uh = make_uint2((uint32_t)hx | ((uint32_t)hy << 16), (uint32_t)hz | ((uint32_t)hw << 16));
    unsigned short lx = f2bf(v.x - bf2f(hx)), ly = f2bf(v.y - bf2f(hy));
    unsigned short lz = f2bf(v.z - bf2f(hz)), lw = f2bf(v.w - bf2f(hw));
    ul = make_uint2((uint32_t)lx | ((uint32_t)ly << 16), (uint32_t)lz | ((uint32_t)lw << 16));
}
// 2 packed fp16 -> packed bf16 hi + packed bf16 lo
__device__ __forceinline__ void h2_to_bf(uint32_t u, uint32_t& hi, uint32_t& lo) {
    float2 f = __half22float2(*(__half2*)&u);
    unsigned short h0 = f2bf(f.x), h1 = f2bf(f.y);
    unsigned short l0 = f2bf(f.x - bf2f(h0)), l1 = f2bf(f.y - bf2f(h1));
    hi = (uint32_t)h0 | ((uint32_t)h1 << 16);
    lo = (uint32_t)l0 | ((uint32_t)l1 << 16);
}

// ---------------- edge_index dtype detection ----------------
__global__ void k_detect(const int* __restrict__ ei32) {
    __shared__ int nz;
    if (threadIdx.x == 0) nz = 0;
    __syncthreads();
    int local = 0;
    for (int i = threadIdx.x; i < 4096; i += blockDim.x)
        if (ei32[2 * i + 1] != 0) local = 1;
    if (local) atomicOr(&nz, 1);
    __syncthreads();
    if (threadIdx.x == 0) g_is64 = (nz == 0) ? 1 : 0;
}
__device__ __forceinline__ int load_edge(const void* ei, int idx, int is64) {
    int v;
    if (is64) v = (int)((const long long*)ei)[idx];
    else      v = ((const int*)ei)[idx];
    v = v < 0 ? 0 : (v >= NN ? NN - 1 : v);
    return v;
}

// ---------------- CSR build ----------------
__global__ void k_zero() {
    int i = blockIdx.x * blockDim.x + threadIdx.x;
    if (i < NN) { g_deg[i] = 0; g_fill[i] = 0; }
}
__global__ void k_hist(const void* __restrict__ ei) {
    int e = blockIdx.x * blockDim.x + threadIdx.x;
    if (e < NE) atomicAdd(&g_deg[load_edge(ei, NE + e, g_is64)], 1);
}
__global__ void k_scan_local() {
    __shared__ int s[2][SCAN_B];
    int t = threadIdx.x, gid = blockIdx.x * SCAN_B + t;
    int v = (gid < NN) ? g_deg[gid] : 0;
    int cur = 0;
    s[0][t] = v;
    __syncthreads();
    for (int off = 1; off < SCAN_B; off <<= 1) {
        int add = (t >= off) ? s[cur][t - off] : 0;
        s[cur ^ 1][t] = s[cur][t] + add;
        cur ^= 1;
        __syncthreads();
    }
    int incl = s[cur][t];
    if (gid < NN) g_rowptr[gid] = incl - v;
    if (t == SCAN_B - 1) g_bsum[blockIdx.x] = incl;
}
__global__ void k_scan_off() {
    if (blockIdx.x == 0 && threadIdx.x == 0) {
        int run = 0;
        for (int b = 0; b < NSB; b++) { int tmp = g_bsum[b]; g_bsum[b] = run; run += tmp; }
    }
}
__global__ void k_scan_add() {
    int gid = blockIdx.x * SCAN_B + threadIdx.x;
    if (gid < NN) {
        g_rowptr[gid] += g_bsum[blockIdx.x];
        int d = g_deg[gid];
        g_deginv[gid] = 1.0f / (float)(d > 1 ? d : 1);
    }
}
__global__ void k_fill(const void* __restrict__ ei) {
    int e = blockIdx.x * blockDim.x + threadIdx.x;
    if (e < NE) {
        int is64 = g_is64;
        int d = load_edge(ei, NE + e, is64);
        int s = load_edge(ei, e, is64);
        int pos = g_rowptr[d] + atomicAdd(&g_fill[d], 1);
        g_col[pos] = s;
    }
}

// ---------------- prep: x -> fp16 buffer A (layer-1 state) ----------------
__global__ void k_prepA(const float* __restrict__ x) {
    int id = blockIdx.x * blockDim.x + threadIdx.x;      // NN*32
    if (id >= NN * 32) return;
    int row = id >> 5, k4 = id & 31;
    float4 v = __ldg((const float4*)(x + (size_t)row * DD) + k4);
    __half2 a = __floats2half2_rn(v.x, v.y);
    __half2 b = __floats2half2_rn(v.z, v.w);
    uint2 u = make_uint2(*(uint32_t*)&a, *(uint32_t*)&b);
    ((uint2*)g_hA)[(size_t)row * 32 + k4] = u;
}

// ---------------- prep: weights -> packed hi/lo B ([layer][n][K=256]) ----------------
__global__ void k_prepW(const float* __restrict__ W1l, const float* __restrict__ W1r,
                        const float* __restrict__ W2l, const float* __restrict__ W2r,
                        const float* __restrict__ W3l, const float* __restrict__ W3r) {
    int id = blockIdx.x * blockDim.x + threadIdx.x;      // 3*128*64
    if (id >= 3 * 128 * 64) return;
    int layer = id >> 13;
    int rem = id & 8191;
    int n = rem >> 6, kq = rem & 63;
    int k = kq * 4;
    const float* Wl = layer == 0 ? W1l : (layer == 1 ? W2l : W3l);
    const float* Wr = layer == 0 ? W1r : (layer == 1 ? W2r : W3r);
    float4 v = (k < 128) ? __ldg((const float4*)(Wl + n * DD + k))
                         : __ldg((const float4*)(Wr + n * DD + (k - 128)));
    unsigned short h0 = f2bf(v.x), h1 = f2bf(v.y), h2 = f2bf(v.z), h3 = f2bf(v.w);
    unsigned short l0 = f2bf(v.x - bf2f(h0)), l1 = f2bf(v.y - bf2f(h1));
    unsigned short l2 = f2bf(v.z - bf2f(h2)), l3 = f2bf(v.w - bf2f(h3));
    uint2* dst = g_Bpk + (size_t)layer * 128 * 128 + n * 128 + (k >> 1);
    dst[0] = make_uint2((uint32_t)h0 | ((uint32_t)h1 << 16), (uint32_t)l0 | ((uint32_t)l1 << 16));
    dst[1] = make_uint2((uint32_t)h2 | ((uint32_t)h3 << 16), (uint32_t)l2 | ((uint32_t)l3 << 16));
}

// ---------------- fused layer: gather + MMA + epilogue (double-buffered h) ----------------
// Block = 32 nodes, 256 threads / 8 warps.
// hsel: 0 = read g_hA / write g_hB; 1 = read g_hB / write g_hA. Last layer writes fp32 out.
__global__ void __launch_bounds__(256) k_fused(
    int layer, int hsel, const float* __restrict__ bias, float* __restrict__ outp, int last)
{
    __shared__ __align__(16) unsigned char sAhi[32 * 512];   // 16 KB
    __shared__ __align__(16) unsigned char sAlo[32 * 512];   // 16 KB
    __shared__ float sBias[128];

    int tid = threadIdx.x, wid = tid >> 5, lane = tid & 31;
    int rowBase = blockIdx.x * MTILE;
    const __half* hr = (hsel == 0) ? g_hA : g_hB;            // read buffer
    __half*       hw = (hsel == 0) ? g_hB : g_hA;            // write buffer
    const uint2* __restrict__ H = (const uint2*)hr;          // row = 32 uint2 (128 fp16)

    // ---- self half (cols 128..255): 32 rows x 16 uint4; 2 per thread ----
    {
        const uint4* hS = (const uint4*)hr + (size_t)rowBase * 16;
#pragma unroll
        for (int it = 0; it < 2; it++) {
            int idx = it * 256 + tid;
            int r = idx >> 4, u = idx & 15;
            uint4 hv = __ldg(&hS[r * 16 + u]);
            uint4 Hh, Ll;
            h2_to_bf(hv.x, Hh.x, Ll.x);
            h2_to_bf(hv.y, Hh.y, Ll.y);
            h2_to_bf(hv.z, Hh.z, Ll.z);
            h2_to_bf(hv.w, Hh.w, Ll.w);
            int c16 = 16 + u;
            uint32_t off = (uint32_t)(r * 512 + ((c16 ^ (r & 7)) << 4));
            *(uint4*)(sAhi + off) = Hh;
            *(uint4*)(sAlo + off) = Ll;
        }
        if (tid < 128) sBias[tid] = __ldg(&bias[tid]);
    }

    // ---- gather phase: warp wid handles 4 nodes ----
#pragma unroll 1
    for (int s = 0; s < 4; s++) {
        int r = (wid << 2) + s;                  // local row 0..31
        int w = rowBase + r;
        int base = __ldg(&g_rowptr[w]);
        int cnt  = __ldg(&g_deg[w]);

        float4 acc = make_float4(0.f, 0.f, 0.f, 0.f);
#define ACC(u) { float2 f0 = __half22float2(*(__half2*)&(u).x); \
                 float2 f1 = __half22float2(*(__half2*)&(u).y); \
                 acc.x += f0.x; acc.y += f0.y; acc.z += f1.x; acc.w += f1.y; }
        int t = 0;
        for (; t + 8 <= cnt; t += 8) {
            int j[8];
#pragma unroll
            for (int q = 0; q < 8; q++) j[q] = __ldg(&g_col[base + t + q]);
            uint2 u[8];
#pragma unroll
            for (int q = 0; q < 8; q++) u[q] = __ldg(&H[(size_t)j[q] * 32 + lane]);
#pragma unroll
            for (int q = 0; q < 8; q++) ACC(u[q])
        }
        if (t + 4 <= cnt) {
            int j[4];
#pragma unroll
            for (int q = 0; q < 4; q++) j[q] = __ldg(&g_col[base + t + q]);
            uint2 u[4];
#pragma unroll
            for (int q = 0; q < 4; q++) u[q] = __ldg(&H[(size_t)j[q] * 32 + lane]);
#pragma unroll
            for (int q = 0; q < 4; q++) ACC(u[q])
            t += 4;
        }
        for (; t < cnt; t++) {
            int j = __ldg(&g_col[base + t]);
            uint2 u = __ldg(&H[(size_t)j * 32 + lane]);
            ACC(u)
        }
#undef ACC
        float di = __ldg(&g_deginv[w]);
        float4 o = make_float4(acc.x * di, acc.y * di, acc.z * di, acc.w * di);

        uint2 uh, ul;
        split4(o, uh, ul);
        int c16 = lane >> 1, half = lane & 1;
        uint32_t off = (uint32_t)(r * 512 + ((c16 ^ (r & 7)) << 4) + half * 8);
        *(uint2*)(sAhi + off) = uh;
        *(uint2*)(sAlo + off) = ul;
    }
    __syncthreads();

    // ---- MMA phase ----
    uint32_t aHiBase = smem_u32(sAhi);
    uint32_t aLoBase = smem_u32(sAlo);
    int wm = wid & 1, wn = wid >> 1;
    const uint2* __restrict__ Bpk = g_Bpk + (size_t)layer * 128 * 128;

    float acc[4][4];
#pragma unroll
    for (int nt = 0; nt < 4; nt++)
#pragma unroll
        for (int q = 0; q < 4; q++) acc[nt][q] = 0.0f;

#pragma unroll
    for (int ks = 0; ks < 16; ks++) {
        uint32_t ah[4], al[4];
        {
            int r = wm * 16 + (lane & 15);
            int c16 = ks * 2 + (lane >> 4);
            uint32_t off = (uint32_t)(r * 512 + ((c16 ^ (r & 7)) << 4));
            ldmatrix_x4(ah[0], ah[1], ah[2], ah[3], aHiBase + off);
            ldmatrix_x4(al[0], al[1], al[2], al[3], aLoBase + off);
        }
        uint32_t bh[4][2], bl[4][2];
#pragma unroll
        for (int nt = 0; nt < 4; nt++) {
            int n = wn * 32 + nt * 8 + (lane >> 2);
            int kb = ks * 16 + (lane & 3) * 2;
            uint2 p0 = __ldg(&Bpk[n * 128 + (kb >> 1)]);
            uint2 p1 = __ldg(&Bpk[n * 128 + ((kb + 8) >> 1)]);
            bh[nt][0] = p0.x; bh[nt][1] = p1.x;
            bl[nt][0] = p0.y; bl[nt][1] = p1.y;
        }
#pragma unroll
        for (int nt = 0; nt < 4; nt++) {
            mma_bf16(acc[nt], ah, bh[nt]);
            mma_bf16(acc[nt], ah, bl[nt]);
            mma_bf16(acc[nt], al, bh[nt]);
        }
    }

    // ---- epilogue: +bias, (ReLU), write h16 to the OTHER buffer (or fp32 out if last) ----
    int r0 = rowBase + wm * 16 + (lane >> 2);
#pragma unroll
    for (int nt = 0; nt < 4; nt++) {
        int col = wn * 32 + nt * 8 + (lane & 3) * 2;
        float b0 = sBias[col], b1 = sBias[col + 1];
        float2 v01 = make_float2(acc[nt][0] + b0, acc[nt][1] + b1);
        float2 v23 = make_float2(acc[nt][2] + b0, acc[nt][3] + b1);
        if (!last) {
            v01.x = fmaxf(v01.x, 0.f); v01.y = fmaxf(v01.y, 0.f);
            v23.x = fmaxf(v23.x, 0.f); v23.y = fmaxf(v23.y, 0.f);
        }
        if (last) {
            *(float2*)(outp + (size_t)r0 * DD + col)       = v01;
            *(float2*)(outp + (size_t)(r0 + 8) * DD + col) = v23;
        } else {
            __half2 h01 = __floats2half2_rn(v01.x, v01.y);
            __half2 h23 = __floats2half2_rn(v23.x, v23.y);
            *(__half2*)(hw + (size_t)r0 * DD + col)       = h01;
            *(__half2*)(hw + (size_t)(r0 + 8) * DD + col) = h23;
        }
    }
}

// ---------------- launch ----------------
extern "C" void kernel_launch(void* const* d_in, const int* in_sizes, int n_in,
                              void* d_out, int out_size)
{
    const float* x  = nullptr;
    const void*  ei = nullptr;
    const float* Wm[6] = {nullptr, nullptr, nullptr, nullptr, nullptr, nullptr};
    const float* Bm[3] = {nullptr, nullptr, nullptr};
    int nw = 0, nb = 0;
    for (int i = 0; i < n_in; i++) {
        long long sz = in_sizes[i];
        if (sz == (long long)NN * DD)      x  = (const float*)d_in[i];
        else if (sz == (long long)2 * NE)  ei = d_in[i];
        else if (sz == (long long)NE)      { /* edge_attr, unused */ }
        else if (sz == DD * DD)            { if (nw < 6) Wm[nw++] = (const float*)d_in[i]; }
        else if (sz == DD)                 { if (nb < 3) Bm[nb++] = (const float*)d_in[i]; }
    }
    float* out = (float*)d_out;
    if (!x || !ei || nw < 6 || nb < 3) return;

    const int EB = (NE + 255) / 256;
    const int NB = (NN + 255) / 256;
    const int PA = (NN * 32 + 255) / 256;
    const int PW = (3 * 128 * 64 + 255) / 256;

    // CSR build
    k_detect<<<1, 256>>>((const int*)ei);
    k_zero<<<NB, 256>>>();
    k_hist<<<EB, 256>>>(ei);
    k_scan_local<<<NSB, SCAN_B>>>();
    k_scan_off<<<1, 32>>>();
    k_scan_add<<<NSB, SCAN_B>>>();
    k_fill<<<EB, 256>>>(ei);

    // prep
    k_prepA<<<PA, 256>>>(x);
    k_prepW<<<PW, 256>>>(Wm[0], Wm[1], Wm[2], Wm[3], Wm[4], Wm[5]);

    // fused layers (double-buffered: A->B, B->A, A->out)
    k_fused<<<GRIDM, 256>>>(0, 0, Bm[0], nullptr, 0);
    k_fused<<<GRIDM, 256>>>(1, 1, Bm[1], nullptr, 0);
    k_fused<<<GRIDM, 256>>>(2, 0, Bm[2], out, 1);
}

// round 13
// speedup vs baseline: 1.8064x; 1.0411x over previous
#include <cuda_runtime.h>
#include <cuda_fp16.h>
#include <cstdint>

// GraphSAGE 3-layer, mean aggregation — fused layer kernel, fp16-compensated MMA.
// Per layer (one kernel): per block of 32 nodes,
//   warp-gather: agg_i = deg_inv * sum_{j in N(i)} h16[cur]_j  (fp32 accum)
//   MMA: h16[1-cur]_i = act( [agg_i | h16[cur]_i] @ [Wl | Wr]^T + b )
// A/B split fp16 hi+lo (22-bit); self half of A is exact fp16 -> lo==0 -> 2-term MMA.
// Double-buffered h removes cross-block RAW hazard.

#define NN 100000
#define NE 1600000
#define DD 128
#define SCAN_B 1024
#define NSB 98
#define MTILE 32
#define GRIDM 3125                 // 3125*32 == 100000 exactly

// ---------------- static device scratch ----------------
__device__ int   g_deg[NN];
__device__ int   g_fill[NN];
__device__ int   g_rowptr[NN];
__device__ float g_deginv[NN];
__device__ int   g_col[NE];
__device__ int   g_bsum[NSB];
__device__ int   g_is64;
__device__ __align__(16) __half g_hA[(size_t)NN * DD];
__device__ __align__(16) __half g_hB[(size_t)NN * DD];
__device__ __align__(16) uint2  g_Bpk[3 * 128 * 128];   // [layer][n][k/2]: x={hi k,k+1}, y={lo k,k+1} (fp16)

// ---------------- helpers ----------------
__device__ __forceinline__ uint32_t smem_u32(const void* p) {
    uint32_t a;
    asm("{ .reg .u64 t; cvta.to.shared.u64 t, %1; cvt.u32.u64 %0, t; }" : "=r"(a) : "l"(p));
    return a;
}
__device__ __forceinline__ void ldmatrix_x4(uint32_t& r0, uint32_t& r1, uint32_t& r2, uint32_t& r3, uint32_t addr) {
    asm volatile("ldmatrix.sync.aligned.m8n8.x4.shared.b16 {%0,%1,%2,%3}, [%4];"
                 : "=r"(r0), "=r"(r1), "=r"(r2), "=r"(r3) : "r"(addr));
}
__device__ __forceinline__ void mma_f16(float* c, const uint32_t* a, const uint32_t* b) {
    asm volatile("mma.sync.aligned.m16n8k16.row.col.f32.f16.f16.f32 "
                 "{%0,%1,%2,%3}, {%4,%5,%6,%7}, {%8,%9}, {%0,%1,%2,%3};"
                 : "+f"(c[0]), "+f"(c[1]), "+f"(c[2]), "+f"(c[3])
                 : "r"(a[0]), "r"(a[1]), "r"(a[2]), "r"(a[3]), "r"(b[0]), "r"(b[1]));
}
__device__ __forceinline__ unsigned short f2h(float f) {
    __half h = __float2half_rn(f);
    return *reinterpret_cast<unsigned short*>(&h);
}
__device__ __forceinline__ float h2f(unsigned short u) {
    __half h = *reinterpret_cast<__half*>(&u);
    return __half2float(h);
}
// float4 -> fp16 hi pair/pair, fp16 lo pair/pair
__device__ __forceinline__ void split4h(float4 v, uint2& uh, uint2& ul) {
    unsigned short hx = f2h(v.x), hy = f2h(v.y), hz = f2h(v.z), hw = f2h(v.w);
    uh = make_uint2((uint32_t)hx | ((uint32_t)hy << 16), (uint32_t)hz | ((uint32_t)hw << 16));
    unsigned short lx = f2h(v.x - h2f(hx)), ly = f2h(v.y - h2f(hy));
    unsigned short lz = f2h(v.z - h2f(hz)), lw = f2h(v.w - h2f(hw));
    ul = make_uint2((uint32_t)lx | ((uint32_t)ly << 16), (uint32_t)lz | ((uint32_t)lw << 16));
}

// ---------------- edge_index dtype detect ----------------
__device__ __forceinline__ int load_edge(const void* ei, int idx, int is64) {
    int v;
    if (is64) v = (int)((const long long*)ei)[idx];
    else      v = ((const int*)ei)[idx];
    v = v < 0 ? 0 : (v >= NN ? NN - 1 : v);
    return v;
}

// ---------------- CSR build (detect merged into zero) ----------------
__global__ void k_zero_detect(const int* __restrict__ ei32) {
    int i = blockIdx.x * blockDim.x + threadIdx.x;
    if (i < NN) { g_deg[i] = 0; g_fill[i] = 0; }
    if (blockIdx.x == 0) {
        __shared__ int nz;
        if (threadIdx.x == 0) nz = 0;
        __syncthreads();
        int local = 0;
        for (int t = threadIdx.x; t < 4096; t += blockDim.x)
            if (ei32[2 * t + 1] != 0) local = 1;
        if (local) atomicOr(&nz, 1);
        __syncthreads();
        if (threadIdx.x == 0) g_is64 = (nz == 0) ? 1 : 0;
    }
}
__global__ void k_hist(const void* __restrict__ ei) {
    int e = blockIdx.x * blockDim.x + threadIdx.x;
    if (e < NE) atomicAdd(&g_deg[load_edge(ei, NE + e, g_is64)], 1);
}
__global__ void k_scan_local() {
    __shared__ int s[2][SCAN_B];
    int t = threadIdx.x, gid = blockIdx.x * SCAN_B + t;
    int v = (gid < NN) ? g_deg[gid] : 0;
    int cur = 0;
    s[0][t] = v;
    __syncthreads();
    for (int off = 1; off < SCAN_B; off <<= 1) {
        int add = (t >= off) ? s[cur][t - off] : 0;
        s[cur ^ 1][t] = s[cur][t] + add;
        cur ^= 1;
        __syncthreads();
    }
    int incl = s[cur][t];
    if (gid < NN) g_rowptr[gid] = incl - v;
    if (t == SCAN_B - 1) g_bsum[blockIdx.x] = incl;
}
// scan_off folded in: each block prefixes g_bsum itself (98 elements, smem)
__global__ void k_scan_add() {
    __shared__ int sb[NSB];
    __shared__ int pre;
    int t = threadIdx.x;
    if (t < NSB) sb[t] = g_bsum[t];
    __syncthreads();
    if (t == 0) {
        int run = 0;
        for (int b = 0; b < (int)blockIdx.x; b++) run += sb[b];
        pre = run;
    }
    __syncthreads();
    int gid = blockIdx.x * SCAN_B + t;
    if (gid < NN) {
        g_rowptr[gid] += pre;
        int d = g_deg[gid];
        g_deginv[gid] = 1.0f / (float)(d > 1 ? d : 1);
    }
}
__global__ void k_fill(const void* __restrict__ ei) {
    int e = blockIdx.x * blockDim.x + threadIdx.x;
    if (e < NE) {
        int is64 = g_is64;
        int d = load_edge(ei, NE + e, is64);
        int s = load_edge(ei, e, is64);
        int pos = g_rowptr[d] + atomicAdd(&g_fill[d], 1);
        g_col[pos] = s;
    }
}

// ---------------- prep: x -> fp16 buffer A ----------------
__global__ void k_prepA(const float* __restrict__ x) {
    int id = blockIdx.x * blockDim.x + threadIdx.x;      // NN*32
    if (id >= NN * 32) return;
    int row = id >> 5, k4 = id & 31;
    float4 v = __ldg((const float4*)(x + (size_t)row * DD) + k4);
    __half2 a = __floats2half2_rn(v.x, v.y);
    __half2 b = __floats2half2_rn(v.z, v.w);
    uint2 u = make_uint2(*(uint32_t*)&a, *(uint32_t*)&b);
    ((uint2*)g_hA)[(size_t)row * 32 + k4] = u;
}

// ---------------- prep: weights -> packed fp16 hi/lo B ([layer][n][K=256]) ----------------
__global__ void k_prepW(const float* __restrict__ W1l, const float* __restrict__ W1r,
                        const float* __restrict__ W2l, const float* __restrict__ W2r,
                        const float* __restrict__ W3l, const float* __restrict__ W3r) {
    int id = blockIdx.x * blockDim.x + threadIdx.x;      // 3*128*64
    if (id >= 3 * 128 * 64) return;
    int layer = id >> 13;
    int rem = id & 8191;
    int n = rem >> 6, kq = rem & 63;
    int k = kq * 4;
    const float* Wl = layer == 0 ? W1l : (layer == 1 ? W2l : W3l);
    const float* Wr = layer == 0 ? W1r : (layer == 1 ? W2r : W3r);
    float4 v = (k < 128) ? __ldg((const float4*)(Wl + n * DD + k))
                         : __ldg((const float4*)(Wr + n * DD + (k - 128)));
    uint2 uh, ul;
    split4h(v, uh, ul);
    uint2* dst = g_Bpk + (size_t)layer * 128 * 128 + n * 128 + (k >> 1);
    dst[0] = make_uint2(uh.x, ul.x);
    dst[1] = make_uint2(uh.y, ul.y);
}

// ---------------- fused layer: gather + MMA + epilogue (double-buffered h) ----------------
__global__ void __launch_bounds__(256) k_fused(
    int layer, int hsel, const float* __restrict__ bias, float* __restrict__ outp, int last)
{
    __shared__ __align__(16) unsigned char sAhi[32 * 512];   // 16 KB (fp16)
    __shared__ __align__(16) unsigned char sAlo[32 * 512];   // 16 KB (fp16; self half unused)
    __shared__ float sBias[128];

    int tid = threadIdx.x, wid = tid >> 5, lane = tid & 31;
    int rowBase = blockIdx.x * MTILE;
    const __half* hr = (hsel == 0) ? g_hA : g_hB;            // read buffer
    __half*       hw = (hsel == 0) ? g_hB : g_hA;            // write buffer
    const uint2* __restrict__ H = (const uint2*)hr;          // row = 32 uint2 (128 fp16)

    // ---- self half (cols 128..255): exact fp16, direct copy; lo == 0 (never read) ----
    {
        const uint4* hS = (const uint4*)hr + (size_t)rowBase * 16;
#pragma unroll
        for (int it = 0; it < 2; it++) {
            int idx = it * 256 + tid;
            int r = idx >> 4, u = idx & 15;
            uint4 hv = __ldg(&hS[r * 16 + u]);
            int c16 = 16 + u;
            uint32_t off = (uint32_t)(r * 512 + ((c16 ^ (r & 7)) << 4));
            *(uint4*)(sAhi + off) = hv;
        }
        if (tid < 128) sBias[tid] = __ldg(&bias[tid]);
    }

    // ---- gather phase: warp wid handles 4 nodes ----
#pragma unroll 1
    for (int s = 0; s < 4; s++) {
        int r = (wid << 2) + s;                  // local row 0..31
        int w = rowBase + r;
        int base = __ldg(&g_rowptr[w]);
        int cnt  = __ldg(&g_deg[w]);

        float4 acc = make_float4(0.f, 0.f, 0.f, 0.f);
#define ACC(u) { float2 f0 = __half22float2(*(__half2*)&(u).x); \
                 float2 f1 = __half22float2(*(__half2*)&(u).y); \
                 acc.x += f0.x; acc.y += f0.y; acc.z += f1.x; acc.w += f1.y; }
        int t = 0;
        for (; t + 8 <= cnt; t += 8) {
            int j[8];
#pragma unroll
            for (int q = 0; q < 8; q++) j[q] = __ldg(&g_col[base + t + q]);
            uint2 u[8];
#pragma unroll
            for (int q = 0; q < 8; q++) u[q] = __ldg(&H[(size_t)j[q] * 32 + lane]);
#pragma unroll
            for (int q = 0; q < 8; q++) ACC(u[q])
        }
        if (t + 4 <= cnt) {
            int j[4];
#pragma unroll
            for (int q = 0; q < 4; q++) j[q] = __ldg(&g_col[base + t + q]);
            uint2 u[4];
#pragma unroll
            for (int q = 0; q < 4; q++) u[q] = __ldg(&H[(size_t)j[q] * 32 + lane]);
#pragma unroll
            for (int q = 0; q < 4; q++) ACC(u[q])
            t += 4;
        }
        for (; t < cnt; t++) {
            int j = __ldg(&g_col[base + t]);
            uint2 u = __ldg(&H[(size_t)j * 32 + lane]);
            ACC(u)
        }
#undef ACC
        float di = __ldg(&g_deginv[w]);
        float4 o = make_float4(acc.x * di, acc.y * di, acc.z * di, acc.w * di);

        uint2 uh, ul;
        split4h(o, uh, ul);
        int c16 = lane >> 1, half = lane & 1;
        uint32_t off = (uint32_t)(r * 512 + ((c16 ^ (r & 7)) << 4) + half * 8);
        *(uint2*)(sAhi + off) = uh;
        *(uint2*)(sAlo + off) = ul;
    }
    __syncthreads();

    // ---- MMA phase: ks 0..7 = agg half (3 terms), ks 8..15 = self half (2 terms, Al==0) ----
    uint32_t aHiBase = smem_u32(sAhi);
    uint32_t aLoBase = smem_u32(sAlo);
    int wm = wid & 1, wn = wid >> 1;
    const uint2* __restrict__ Bpk = g_Bpk + (size_t)layer * 128 * 128;

    float acc[4][4];
#pragma unroll
    for (int nt = 0; nt < 4; nt++)
#pragma unroll
        for (int q = 0; q < 4; q++) acc[nt][q] = 0.0f;

#pragma unroll
    for (int ks = 0; ks < 16; ks++) {
        uint32_t ah[4], al[4];
        {
            int r = wm * 16 + (lane & 15);
            int c16 = ks * 2 + (lane >> 4);
            uint32_t off = (uint32_t)(r * 512 + ((c16 ^ (r & 7)) << 4));
            ldmatrix_x4(ah[0], ah[1], ah[2], ah[3], aHiBase + off);
            if (ks < 8) ldmatrix_x4(al[0], al[1], al[2], al[3], aLoBase + off);
        }
        uint32_t bh[4][2], bl[4][2];
#pragma unroll
        for (int nt = 0; nt < 4; nt++) {
            int n = wn * 32 + nt * 8 + (lane >> 2);
            int kb = ks * 16 + (lane & 3) * 2;
            uint2 p0 = __ldg(&Bpk[n * 128 + (kb >> 1)]);
            uint2 p1 = __ldg(&Bpk[n * 128 + ((kb + 8) >> 1)]);
            bh[nt][0] = p0.x; bh[nt][1] = p1.x;
            bl[nt][0] = p0.y; bl[nt][1] = p1.y;
        }
#pragma unroll
        for (int nt = 0; nt < 4; nt++) {
            mma_f16(acc[nt], ah, bh[nt]);
            mma_f16(acc[nt], ah, bl[nt]);
            if (ks < 8) mma_f16(acc[nt], al, bh[nt]);
        }
    }

    // ---- epilogue: +bias, (ReLU), write h16 to the OTHER buffer (or fp32 out if last) ----
    int r0 = rowBase + wm * 16 + (lane >> 2);
#pragma unroll
    for (int nt = 0; nt < 4; nt++) {
        int col = wn * 32 + nt * 8 + (lane & 3) * 2;
        float b0 = sBias[col], b1 = sBias[col + 1];
        float2 v01 = make_float2(acc[nt][0] + b0, acc[nt][1] + b1);
        float2 v23 = make_float2(acc[nt][2] + b0, acc[nt][3] + b1);
        if (!last) {
            v01.x = fmaxf(v01.x, 0.f); v01.y = fmaxf(v01.y, 0.f);
            v23.x = fmaxf(v23.x, 0.f); v23.y = fmaxf(v23.y, 0.f);
        }
        if (last) {
            *(float2*)(outp + (size_t)r0 * DD + col)       = v01;
            *(float2*)(outp + (size_t)(r0 + 8) * DD + col) = v23;
        } else {
            __half2 h01 = __floats2half2_rn(v01.x, v01.y);
            __half2 h23 = __floats2half2_rn(v23.x, v23.y);
            *(__half2*)(hw + (size_t)r0 * DD + col)       = h01;
            *(__half2*)(hw + (size_t)(r0 + 8) * DD + col) = h23;
        }
    }
}

// ---------------- launch ----------------
extern "C" void kernel_launch(void* const* d_in, const int* in_sizes, int n_in,
                              void* d_out, int out_size)
{
    const float* x  = nullptr;
    const void*  ei = nullptr;
    const float* Wm[6] = {nullptr, nullptr, nullptr, nullptr, nullptr, nullptr};
    const float* Bm[3] = {nullptr, nullptr, nullptr};
    int nw = 0, nb = 0;
    for (int i = 0; i < n_in; i++) {
        long long sz = in_sizes[i];
        if (sz == (long long)NN * DD)      x  = (const float*)d_in[i];
        else if (sz == (long long)2 * NE)  ei = d_in[i];
        else if (sz == (long long)NE)      { /* edge_attr, unused */ }
        else if (sz == DD * DD)            { if (nw < 6) Wm[nw++] = (const float*)d_in[i]; }
        else if (sz == DD)                 { if (nb < 3) Bm[nb++] = (const float*)d_in[i]; }
    }
    float* out = (float*)d_out;
    if (!x || !ei || nw < 6 || nb < 3) return;

    const int EB = (NE + 255) / 256;
    const int NB = (NN + 255) / 256;
    const int PA = (NN * 32 + 255) / 256;
    const int PW = (3 * 128 * 64 + 255) / 256;

    // CSR build
    k_zero_detect<<<NB, 256>>>((const int*)ei);
    k_hist<<<EB, 256>>>(ei);
    k_scan_local<<<NSB, SCAN_B>>>();
    k_scan_add<<<NSB, SCAN_B>>>();
    k_fill<<<EB, 256>>>(ei);

    // prep
    k_prepA<<<PA, 256>>>(x);
    k_prepW<<<PW, 256>>>(Wm[0], Wm[1], Wm[2], Wm[3], Wm[4], Wm[5]);

    // fused layers (double-buffered: A->B, B->A, A->out)
    k_fused<<<GRIDM, 256>>>(0, 0, Bm[0], nullptr, 0);
    k_fused<<<GRIDM, 256>>>(1, 1, Bm[1], nullptr, 0);
    k_fused<<<GRIDM, 256>>>(2, 0, Bm[2], out, 1);
}

// round 15
// speedup vs baseline: 2.5823x; 1.4295x over previous
#include <cuda_runtime.h>
#include <cuda_fp16.h>
#include <cstdint>

// GraphSAGE 3-layer, mean aggregation — fused layer kernel, fp16-compensated MMA, MTILE=64.
// Per layer (one kernel): per block of 64 nodes,
//   warp-gather: agg_i = deg_inv * sum_{j in N(i)} h16[cur]_j  (fp32 accum)
//   MMA: h16[1-cur]_i = act( [agg_i | h16[cur]_i] @ [Wl | Wr]^T + b )
// A/B split fp16 hi+lo; self half of A exact fp16 -> lo==0 -> 2-term MMA there.
// B packed so each lane's (kb, kb+8) hi/lo fragments form one uint4 (LDG.128).

#define NN 100000
#define NE 1600000
#define DD 128
#define SCAN_B 1024
#define NSB 98
#define MTILE 64
#define GRIDM 1563                 // ceil(100000/64)

// ---------------- static device scratch ----------------
__device__ int   g_deg[NN];
__device__ int   g_fill[NN];
__device__ int   g_rowptr[NN];
__device__ float g_deginv[NN];
__device__ int   g_col[NE];
__device__ int   g_bsum[NSB];
__device__ int   g_is64;
__device__ __align__(16) __half g_hA[(size_t)NN * DD];
__device__ __align__(16) __half g_hB[(size_t)NN * DD];
// [layer][n][ks*4+la]: {hi(k0,k0+1), lo(k0,k0+1), hi(k0+8,k0+9), lo(k0+8,k0+9)}, k0=ks*16+la*2
__device__ __align__(16) uint4  g_Bpk[3 * 128 * 64];

// ---------------- helpers ----------------
__device__ __forceinline__ uint32_t smem_u32(const void* p) {
    uint32_t a;
    asm("{ .reg .u64 t; cvta.to.shared.u64 t, %1; cvt.u32.u64 %0, t; }" : "=r"(a) : "l"(p));
    return a;
}
__device__ __forceinline__ void ldmatrix_x4(uint32_t& r0, uint32_t& r1, uint32_t& r2, uint32_t& r3, uint32_t addr) {
    asm volatile("ldmatrix.sync.aligned.m8n8.x4.shared.b16 {%0,%1,%2,%3}, [%4];"
                 : "=r"(r0), "=r"(r1), "=r"(r2), "=r"(r3) : "r"(addr));
}
__device__ __forceinline__ void mma_f16(float* c, const uint32_t* a, const uint32_t* b) {
    asm volatile("mma.sync.aligned.m16n8k16.row.col.f32.f16.f16.f32 "
                 "{%0,%1,%2,%3}, {%4,%5,%6,%7}, {%8,%9}, {%0,%1,%2,%3};"
                 : "+f"(c[0]), "+f"(c[1]), "+f"(c[2]), "+f"(c[3])
                 : "r"(a[0]), "r"(a[1]), "r"(a[2]), "r"(a[3]), "r"(b[0]), "r"(b[1]));
}
__device__ __forceinline__ unsigned short f2h(float f) {
    __half h = __float2half_rn(f);
    return *reinterpret_cast<unsigned short*>(&h);
}
__device__ __forceinline__ float h2f(unsigned short u) {
    __half h = *reinterpret_cast<__half*>(&u);
    return __half2float(h);
}
__device__ __forceinline__ void split4h(float4 v, uint2& uh, uint2& ul) {
    unsigned short hx = f2h(v.x), hy = f2h(v.y), hz = f2h(v.z), hw = f2h(v.w);
    uh = make_uint2((uint32_t)hx | ((uint32_t)hy << 16), (uint32_t)hz | ((uint32_t)hw << 16));
    unsigned short lx = f2h(v.x - h2f(hx)), ly = f2h(v.y - h2f(hy));
    unsigned short lz = f2h(v.z - h2f(hz)), lw = f2h(v.w - h2f(hw));
    ul = make_uint2((uint32_t)lx | ((uint32_t)ly << 16), (uint32_t)lz | ((uint32_t)lw << 16));
}

// ---------------- edge load ----------------
__device__ __forceinline__ int load_edge(const void* ei, int idx, int is64) {
    int v;
    if (is64) v = (int)((const long long*)ei)[idx];
    else      v = ((const int*)ei)[idx];
    v = v < 0 ? 0 : (v >= NN ? NN - 1 : v);
    return v;
}

// ---------------- CSR build ----------------
__global__ void k_zero_detect(const int* __restrict__ ei32) {
    int i = blockIdx.x * blockDim.x + threadIdx.x;
    if (i < NN) { g_deg[i] = 0; g_fill[i] = 0; }
    if (blockIdx.x == 0) {
        __shared__ int nz;
        if (threadIdx.x == 0) nz = 0;
        __syncthreads();
        int local = 0;
        for (int t = threadIdx.x; t < 4096; t += blockDim.x)
            if (ei32[2 * t + 1] != 0) local = 1;
        if (local) atomicOr(&nz, 1);
        __syncthreads();
        if (threadIdx.x == 0) g_is64 = (nz == 0) ? 1 : 0;
    }
}
__global__ void k_hist(const void* __restrict__ ei) {
    int e = blockIdx.x * blockDim.x + threadIdx.x;
    if (e < NE) atomicAdd(&g_deg[load_edge(ei, NE + e, g_is64)], 1);
}
__global__ void k_scan_local() {
    __shared__ int s[2][SCAN_B];
    int t = threadIdx.x, gid = blockIdx.x * SCAN_B + t;
    int v = (gid < NN) ? g_deg[gid] : 0;
    int cur = 0;
    s[0][t] = v;
    __syncthreads();
    for (int off = 1; off < SCAN_B; off <<= 1) {
        int add = (t >= off) ? s[cur][t - off] : 0;
        s[cur ^ 1][t] = s[cur][t] + add;
        cur ^= 1;
        __syncthreads();
    }
    int incl = s[cur][t];
    if (gid < NN) g_rowptr[gid] = incl - v;
    if (t == SCAN_B - 1) g_bsum[blockIdx.x] = incl;
}
__global__ void k_scan_add() {
    __shared__ int sb[NSB];
    __shared__ int pre;
    int t = threadIdx.x;
    if (t < NSB) sb[t] = g_bsum[t];
    __syncthreads();
    if (t == 0) {
        int run = 0;
        for (int b = 0; b < (int)blockIdx.x; b++) run += sb[b];
        pre = run;
    }
    __syncthreads();
    int gid = blockIdx.x * SCAN_B + t;
    if (gid < NN) {
        g_rowptr[gid] += pre;
        int d = g_deg[gid];
        g_deginv[gid] = 1.0f / (float)(d > 1 ? d : 1);
    }
}
__global__ void k_fill(const void* __restrict__ ei) {
    int e = blockIdx.x * blockDim.x + threadIdx.x;
    if (e < NE) {
        int is64 = g_is64;
        int d = load_edge(ei, NE + e, is64);
        int s = load_edge(ei, e, is64);
        int pos = g_rowptr[d] + atomicAdd(&g_fill[d], 1);
        g_col[pos] = s;
    }
}

// ---------------- prep: x -> fp16 buffer A ----------------
__global__ void k_prepA(const float* __restrict__ x) {
    int id = blockIdx.x * blockDim.x + threadIdx.x;      // NN*32
    if (id >= NN * 32) return;
    int row = id >> 5, k4 = id & 31;
    float4 v = __ldg((const float4*)(x + (size_t)row * DD) + k4);
    __half2 a = __floats2half2_rn(v.x, v.y);
    __half2 b = __floats2half2_rn(v.z, v.w);
    uint2 u = make_uint2(*(uint32_t*)&a, *(uint32_t*)&b);
    ((uint2*)g_hA)[(size_t)row * 32 + k4] = u;
}

// ---------------- prep: weights -> packed fp16 hi/lo B (fragment-pair layout) ----------------
__global__ void k_prepW(const float* __restrict__ W1l, const float* __restrict__ W1r,
                        const float* __restrict__ W2l, const float* __restrict__ W2r,
                        const float* __restrict__ W3l, const float* __restrict__ W3r) {
    int id = blockIdx.x * blockDim.x + threadIdx.x;      // 3*128*64
    if (id >= 3 * 128 * 64) return;
    int layer = id / 8192;
    int rem = id & 8191;
    int n = rem >> 6, la4 = rem & 63;
    int ks = la4 >> 2, la = la4 & 3;
    int k0 = ks * 16 + la * 2;                           // k0, k0+1, k0+8, k0+9 same 16-block
    const float* Wl = layer == 0 ? W1l : (layer == 1 ? W2l : W3l);
    const float* Wr = layer == 0 ? W1r : (layer == 1 ? W2r : W3r);
    const float* row = (k0 < 128) ? (Wl + n * DD) : (Wr + (n * DD - 128));
    float2 v01 = __ldg((const float2*)(row + k0));
    float2 v23 = __ldg((const float2*)(row + k0 + 8));
    unsigned short h0 = f2h(v01.x), h1 = f2h(v01.y), h2 = f2h(v23.x), h3 = f2h(v23.y);
    unsigned short l0 = f2h(v01.x - h2f(h0)), l1 = f2h(v01.y - h2f(h1));
    unsigned short l2 = f2h(v23.x - h2f(h2)), l3 = f2h(v23.y - h2f(h3));
    g_Bpk[layer * 8192 + n * 64 + la4] = make_uint4(
        (uint32_t)h0 | ((uint32_t)h1 << 16), (uint32_t)l0 | ((uint32_t)l1 << 16),
        (uint32_t)h2 | ((uint32_t)h3 << 16), (uint32_t)l2 | ((uint32_t)l3 << 16));
}

// ---------------- fused layer: gather + MMA + epilogue (double-buffered h) ----------------
// Block = 64 nodes, 256 threads / 8 warps. wm = wid&1 (32-row group), wn = wid>>1 (32-col group).
__global__ void __launch_bounds__(256) k_fused(
    int layer, int hsel, const float* __restrict__ bias, float* __restrict__ outp, int last)
{
    __shared__ __align__(16) unsigned char sAhi[64 * 512];   // 32 KB (fp16, K=256)
    __shared__ __align__(16) unsigned char sAlo[64 * 256];   // 16 KB (fp16, agg half only)

    int tid = threadIdx.x, wid = tid >> 5, lane = tid & 31;
    int rowBase = blockIdx.x * MTILE;
    const __half* hr = (hsel == 0) ? g_hA : g_hB;            // read buffer
    __half*       hw = (hsel == 0) ? g_hB : g_hA;            // write buffer
    const uint2* __restrict__ H = (const uint2*)hr;          // row = 32 uint2 (128 fp16)

    // ---- self half (cols 128..255): exact fp16 copy; 64 rows x 16 uint4, 4 per thread ----
    {
        const uint4* hS = (const uint4*)hr + (size_t)rowBase * 16;
#pragma unroll
        for (int it = 0; it < 4; it++) {
            int idx = it * 256 + tid;
            int r = idx >> 4, u = idx & 15;
            uint4 hv = make_uint4(0u, 0u, 0u, 0u);
            if (rowBase + r < NN) hv = __ldg(&hS[r * 16 + u]);
            int c16 = 16 + u;
            uint32_t off = (uint32_t)(r * 512 + ((c16 ^ (r & 7)) << 4));
            *(uint4*)(sAhi + off) = hv;
        }
    }

    // ---- gather phase: warp wid handles 8 nodes ----
#pragma unroll 1
    for (int s = 0; s < 8; s++) {
        int r = (wid << 3) + s;                  // local row 0..63
        int w = rowBase + r;
        float4 o = make_float4(0.f, 0.f, 0.f, 0.f);
        if (w < NN) {
            int base = __ldg(&g_rowptr[w]);
            int cnt  = __ldg(&g_deg[w]);
            float4 acc = make_float4(0.f, 0.f, 0.f, 0.f);
#define ACC(u) { float2 f0 = __half22float2(*(__half2*)&(u).x); \
                 float2 f1 = __half22float2(*(__half2*)&(u).y); \
                 acc.x += f0.x; acc.y += f0.y; acc.z += f1.x; acc.w += f1.y; }
            int t = 0;
            for (; t + 8 <= cnt; t += 8) {
                int j[8];
#pragma unroll
                for (int q = 0; q < 8; q++) j[q] = __ldg(&g_col[base + t + q]);
                uint2 u[8];
#pragma unroll
                for (int q = 0; q < 8; q++) u[q] = __ldg(&H[(size_t)j[q] * 32 + lane]);
#pragma unroll
                for (int q = 0; q < 8; q++) ACC(u[q])
            }
            if (t + 4 <= cnt) {
                int j[4];
#pragma unroll
                for (int q = 0; q < 4; q++) j[q] = __ldg(&g_col[base + t + q]);
                uint2 u[4];
#pragma unroll
                for (int q = 0; q < 4; q++) u[q] = __ldg(&H[(size_t)j[q] * 32 + lane]);
#pragma unroll
                for (int q = 0; q < 4; q++) ACC(u[q])
                t += 4;
            }
            for (; t < cnt; t++) {
                int j = __ldg(&g_col[base + t]);
                uint2 u = __ldg(&H[(size_t)j * 32 + lane]);
                ACC(u)
            }
#undef ACC
            float di = __ldg(&g_deginv[w]);
            o = make_float4(acc.x * di, acc.y * di, acc.z * di, acc.w * di);
        }
        uint2 uh, ul;
        split4h(o, uh, ul);
        int c16 = lane >> 1, half = lane & 1;
        uint32_t sw = (uint32_t)((c16 ^ (r & 7)) << 4) + half * 8;
        *(uint2*)(sAhi + r * 512 + sw) = uh;
        *(uint2*)(sAlo + r * 256 + sw) = ul;
    }
    __syncthreads();

    // ---- MMA phase: ks 0..7 = agg half (3 terms), ks 8..15 = self half (2 terms) ----
    uint32_t aHiBase = smem_u32(sAhi);
    uint32_t aLoBase = smem_u32(sAlo);
    int wm = wid & 1, wn = wid >> 1;
    const uint4* __restrict__ Bpk = g_Bpk + (size_t)layer * 8192;

    float acc[2][4][4];
#pragma unroll
    for (int mt = 0; mt < 2; mt++)
#pragma unroll
        for (int nt = 0; nt < 4; nt++)
#pragma unroll
            for (int q = 0; q < 4; q++) acc[mt][nt][q] = 0.0f;

#pragma unroll
    for (int ks = 0; ks < 16; ks++) {
        uint32_t ah[2][4], al[2][4];
#pragma unroll
        for (int mt = 0; mt < 2; mt++) {
            int r = wm * 32 + mt * 16 + (lane & 15);
            int c16 = ks * 2 + (lane >> 4);
            uint32_t sw = (uint32_t)((c16 ^ (r & 7)) << 4);
            ldmatrix_x4(ah[mt][0], ah[mt][1], ah[mt][2], ah[mt][3], aHiBase + r * 512 + sw);
            if (ks < 8)
                ldmatrix_x4(al[mt][0], al[mt][1], al[mt][2], al[mt][3], aLoBase + r * 256 + sw);
        }
        uint32_t bh[4][2], bl[4][2];
#pragma unroll
        for (int nt = 0; nt < 4; nt++) {
            int n = wn * 32 + nt * 8 + (lane >> 2);
            uint4 p = __ldg(&Bpk[n * 64 + ks * 4 + (lane & 3)]);
            bh[nt][0] = p.x; bh[nt][1] = p.z;
            bl[nt][0] = p.y; bl[nt][1] = p.w;
        }
#pragma unroll
        for (int nt = 0; nt < 4; nt++)
#pragma unroll
            for (int mt = 0; mt < 2; mt++) {
                mma_f16(acc[mt][nt], ah[mt], bh[nt]);
                mma_f16(acc[mt][nt], ah[mt], bl[nt]);
                if (ks < 8) mma_f16(acc[mt][nt], al[mt], bh[nt]);
            }
    }

    // ---- epilogue: +bias (direct ldg), (ReLU), write h16 / fp32 out ----
#pragma unroll
    for (int mt = 0; mt < 2; mt++) {
        int r0 = rowBase + wm * 32 + mt * 16 + (lane >> 2);
#pragma unroll
        for (int nt = 0; nt < 4; nt++) {
            int col = wn * 32 + nt * 8 + (lane & 3) * 2;
            float2 b = __ldg((const float2*)(bias + col));
            float2 v01 = make_float2(acc[mt][nt][0] + b.x, acc[mt][nt][1] + b.y);
            float2 v23 = make_float2(acc[mt][nt][2] + b.x, acc[mt][nt][3] + b.y);
            if (!last) {
                v01.x = fmaxf(v01.x, 0.f); v01.y = fmaxf(v01.y, 0.f);
                v23.x = fmaxf(v23.x, 0.f); v23.y = fmaxf(v23.y, 0.f);
            }
            if (last) {
                if (r0 < NN)     *(float2*)(outp + (size_t)r0 * DD + col)       = v01;
                if (r0 + 8 < NN) *(float2*)(outp + (size_t)(r0 + 8) * DD + col) = v23;
            } else {
                if (r0 < NN) {
                    __half2 hh = __floats2half2_rn(v01.x, v01.y);
                    *(__half2*)(hw + (size_t)r0 * DD + col) = hh;
                }
                if (r0 + 8 < NN) {
                    __half2 hh = __floats2half2_rn(v23.x, v23.y);
                    *(__half2*)(hw + (size_t)(r0 + 8) * DD + col) = hh;
                }
            }
        }
    }
}

// ---------------- launch ----------------
extern "C" void kernel_launch(void* const* d_in, const int* in_sizes, int n_in,
                              void* d_out, int out_size)
{
    const float* x  = nullptr;
    const void*  ei = nullptr;
    const float* Wm[6] = {nullptr, nullptr, nullptr, nullptr, nullptr, nullptr};
    const float* Bm[3] = {nullptr, nullptr, nullptr};
    int nw = 0, nb = 0;
    for (int i = 0; i < n_in; i++) {
        long long sz = in_sizes[i];
        if (sz == (long long)NN * DD)      x  = (const float*)d_in[i];
        else if (sz == (long long)2 * NE)  ei = d_in[i];
        else if (sz == (long long)NE)      { /* edge_attr, unused */ }
        else if (sz == DD * DD)            { if (nw < 6) Wm[nw++] = (const float*)d_in[i]; }
        else if (sz == DD)                 { if (nb < 3) Bm[nb++] = (const float*)d_in[i]; }
    }
    float* out = (float*)d_out;
    if (!x || !ei || nw < 6 || nb < 3) return;

    const int EB = (NE + 255) / 256;
    const int NB = (NN + 255) / 256;
    const int PA = (NN * 32 + 255) / 256;
    const int PW = (3 * 128 * 64 + 255) / 256;

    // CSR build
    k_zero_detect<<<NB, 256>>>((const int*)ei);
    k_hist<<<EB, 256>>>(ei);
    k_scan_local<<<NSB, SCAN_B>>>();
    k_scan_add<<<NSB, SCAN_B>>>();
    k_fill<<<EB, 256>>>(ei);

    // prep
    k_prepA<<<PA, 256>>>(x);
    k_prepW<<<PW, 256>>>(Wm[0], Wm[1], Wm[2], Wm[3], Wm[4], Wm[5]);

    // fused layers (double-buffered: A->B, B->A, A->out)
    k_fused<<<GRIDM, 256>>>(0, 0, Bm[0], nullptr, 0);
    k_fused<<<GRIDM, 256>>>(1, 1, Bm[1], nullptr, 0);
    k_fused<<<GRIDM, 256>>>(2, 0, Bm[2], out, 1);
}